// round 13
// baseline (speedup 1.0000x reference)
#include <cuda_runtime.h>
#include <cuda_bf16.h>
#include <cstdint>

#define NN 12000
#define NE 120000
#define NBLK 938   // ceil(120000/128)

// ---------------- device scratch (allocation-free) ----------------
static __device__ float g_sum[NN * 96];
static __device__ float g_cnt[NN];
// B fragments: 384 nc x 8 kc x 4 t x 8 g, uint4 = [b0hi, b1hi, b0lo, b1lo]
static __device__ uint4 g_B[98304];

// ---------------- smem float-offset layout ----------------
// staging region (emb f32 [128][132]) occupies [0, 16896) and is dead after frag load
#define OF_X1S 0        // [32][128]
#define OF_VD 4096      // [16][128]
#define OF_C6 6144      // [3*16][128]  x1v[k]*y0
#define OF_Y0 12288     // [128]
#define OF_Y1 12416     // [3][128]
#define OF_MSG 12800    // [128][113]  (0..47 s/g, 48..95 v, 96..111 deferred W5 t5)
#define OF_DST 27264    // [128] int
#define OF_SRC 27392    // [128] int
#define SMEM_F 27520
#define SMEM_BYTES (SMEM_F * 4)
#define MROW 113
#define STG_STRIDE 132

__device__ __forceinline__ void split_pair(float a, float b, uint32_t& hi, uint32_t& lo) {
    __nv_bfloat16 ah = __float2bfloat16(a), bh = __float2bfloat16(b);
    float ar = a - __bfloat162float(ah), br = b - __bfloat162float(bh);
    __nv_bfloat16 al = __float2bfloat16(ar), bl = __float2bfloat16(br);
    hi = (uint32_t)__bfloat16_as_ushort(ah) | ((uint32_t)__bfloat16_as_ushort(bh) << 16);
    lo = (uint32_t)__bfloat16_as_ushort(al) | ((uint32_t)__bfloat16_as_ushort(bl) << 16);
}

__device__ __forceinline__ void mma_bf16(float d[4], const uint32_t* a, uint32_t b0, uint32_t b1) {
    asm volatile(
        "mma.sync.aligned.m16n8k16.row.col.f32.bf16.bf16.f32 "
        "{%0,%1,%2,%3}, {%4,%5,%6,%7}, {%8,%9}, {%0,%1,%2,%3};"
        : "+f"(d[0]), "+f"(d[1]), "+f"(d[2]), "+f"(d[3])
        : "r"(a[0]), "r"(a[1]), "r"(a[2]), "r"(a[3]), "r"(b0), "r"(b1));
}

// one 8-col n-chunk: D(16e x 8n) = sum over 8 k-chunks, 3 split products
__device__ __forceinline__ void gemm_chunk(const uint4* __restrict__ bp,
                                           const uint32_t* aHi, const uint32_t* aLo,
                                           float d[4]) {
    float d0[4] = {0.f, 0.f, 0.f, 0.f}, d1[4] = {0.f, 0.f, 0.f, 0.f}, d2[4] = {0.f, 0.f, 0.f, 0.f};
#pragma unroll
    for (int kc = 0; kc < 8; kc++) {
        uint4 b = __ldg(bp + kc * 32);
        mma_bf16(d0, aHi + kc * 4, b.x, b.y);
        mma_bf16(d1, aLo + kc * 4, b.x, b.y);
        mma_bf16(d2, aHi + kc * 4, b.z, b.w);
    }
#pragma unroll
    for (int i = 0; i < 4; i++) d[i] = d0[i] + d1[i] + d2[i];
}

// ---------------- kernel: zero scratch ----------------
__global__ void eq_zero_kernel() {
    int i = blockIdx.x * 256 + threadIdx.x;
    if (i < NN * 96) g_sum[i] = 0.0f;
    if (i < NN) g_cnt[i] = 0.0f;
}

// ---------------- kernel: prep B fragments ----------------
// thread per (n, k-pair): n in 0..3071, pk in 0..63 (kc = pk>>3, p = pk&7)
__global__ void eq_prep_kernel(const float* __restrict__ wm) {
    int idx = blockIdx.x * 256 + threadIdx.x;
    if (idx >= 3072 * 64) return;
    int n = idx >> 6, pk = idx & 63;
    int kc = pk >> 3, p = pk & 7;
    int k = kc * 16 + 2 * p;
    const float RS = 0.08838834764831845f;   // 1/sqrt(128)
    float v0 = wm[(size_t)k * 3072 + n] * RS;
    float v1 = wm[(size_t)(k + 1) * 3072 + n] * RS;
    uint32_t hi, lo;
    split_pair(v0, v1, hi, lo);
    int nc = n >> 3, g = n & 7, t = p & 3, sel = p >> 2;
    uint32_t* gb = (uint32_t*)g_B + ((((size_t)(nc * 8 + kc) * 4 + t) * 8 + g) << 2);
    gb[sel] = hi;
    gb[2 + sel] = lo;
}

// ---------------- main fused edge kernel ----------------
__global__ __launch_bounds__(256, 2) void eq_edge_kernel(
    const float* __restrict__ x, const float* __restrict__ ea,
    const float* __restrict__ Yij, const int* __restrict__ eidx)
{
    extern __shared__ float sm[];
    const int tid = threadIdx.x;
    const int wp = tid >> 5;
    const int lane = tid & 31;
    const int g = lane >> 2;
    const int t = lane & 3;
    const int eb0 = blockIdx.x << 7;
    int* s_dst = (int*)(sm + OF_DST);
    int* s_src = (int*)(sm + OF_SRC);

    if (tid < 128) {
        int eg = eb0 + tid;
        s_dst[tid] = (eg < NE) ? eidx[eg] : 0;
        s_src[tid] = (eg < NE) ? eidx[NE + eg] : 0;
    }
    __syncthreads();

    // ---- stage emb f32 rows [e][132] at smem offset 0 (raw, no scaling) ----
    if (tid < 128) {
        const int e = tid;
        float* row = sm + e * STG_STRIDE;
        const bool valid = (eb0 + e) < NE;
        if (valid) {
            const float4* pd = (const float4*)(x + (size_t)s_dst[e] * 80);
            const float4* ps = (const float4*)(x + (size_t)s_src[e] * 80);
            const float4* pe = (const float4*)(ea + (size_t)(eb0 + e) * 64);
#pragma unroll
            for (int i = 0; i < 8; i++) ((float4*)row)[i] = pd[i];
#pragma unroll
            for (int i = 0; i < 8; i++) ((float4*)(row + 32))[i] = ps[i];
#pragma unroll
            for (int i = 0; i < 16; i++) ((float4*)(row + 64))[i] = pe[i];
        } else {
#pragma unroll
            for (int i = 0; i < 32; i++) ((float4*)row)[i] = make_float4(0.f, 0.f, 0.f, 0.f);
        }
    }
    __syncthreads();

    // ---- load persistent A fragments (hi/lo bf16 split) ----
    const int e1l = wp * 16 + g;
    const int e2l = e1l + 8;
    uint32_t aHi[32], aLo[32];
    {
        const float* r1 = sm + e1l * STG_STRIDE + 2 * t;
        const float* r2 = sm + e2l * STG_STRIDE + 2 * t;
#pragma unroll
        for (int kc = 0; kc < 8; kc++) {
            const float* p1 = r1 + kc * 16;
            const float* p2 = r2 + kc * 16;
            split_pair(p1[0], p1[1], aHi[kc * 4 + 0], aLo[kc * 4 + 0]);
            split_pair(p2[0], p2[1], aHi[kc * 4 + 1], aLo[kc * 4 + 1]);
            split_pair(p1[8], p1[9], aHi[kc * 4 + 2], aLo[kc * 4 + 2]);
            split_pair(p2[8], p2[9], aHi[kc * 4 + 3], aLo[kc * 4 + 3]);
        }
    }
    __syncthreads();

    // ---- zero msg + stage coefficients (staging region now dead) ----
    for (int i = tid; i < 128 * MROW; i += 256) sm[OF_MSG + i] = 0.0f;
    if (tid < 128) {
        const int e = tid;
        const bool valid = (eb0 + e) < NE;
        float4 Y = valid ? *(const float4*)(Yij + (size_t)(eb0 + e) * 4)
                         : make_float4(0.f, 0.f, 0.f, 0.f);
        sm[OF_Y0 + e] = Y.x;
        sm[OF_Y1 + e] = Y.y; sm[OF_Y1 + 128 + e] = Y.z; sm[OF_Y1 + 256 + e] = Y.w;
        const float* xr = x + (size_t)s_src[e] * 80;
        const float INV3 = 0.57735026918962576f;
#pragma unroll
        for (int u = 0; u < 32; u++)
            sm[OF_X1S + (u << 7) + e] = valid ? xr[u] : 0.0f;
#pragma unroll
        for (int u = 0; u < 16; u++) {
            float v0 = valid ? xr[32 + u * 3] : 0.0f;
            float v1 = valid ? xr[33 + u * 3] : 0.0f;
            float v2 = valid ? xr[34 + u * 3] : 0.0f;
            sm[OF_VD + (u << 7) + e] = (v0 * Y.y + v1 * Y.z + v2 * Y.w) * INV3;
            sm[OF_C6 + ((0 * 16 + u) << 7) + e] = v0 * Y.x;
            sm[OF_C6 + ((1 * 16 + u) << 7) + e] = v1 * Y.x;
            sm[OF_C6 + ((2 * 16 + u) << 7) + e] = v2 * Y.x;
        }
    }
    __syncthreads();

    // ---- mainloop: warp-exclusive msg rows, no further syncs ----
    float* m1 = sm + OF_MSG + e1l * MROW;
    float* m2 = sm + OF_MSG + e2l * MROW;
    const float y0a = sm[OF_Y0 + e1l];
    const float y0b = sm[OF_Y0 + e2l];
    const uint4* bbase = g_B + t * 8 + g;
    const int w2t = 2 * t;
    float d[4];

    // W1: nc 0..127, coef x1s*y0 -> s (msg[0..31])
    for (int nc = 0; nc < 128; nc++) {
        gemm_chunk(bbase + nc * 256, aHi, aLo, d);
        int u = nc >> 2, w0 = ((nc & 3) << 3) + w2t;
        float c1 = sm[OF_X1S + (u << 7) + e1l] * y0a;
        float c2 = sm[OF_X1S + (u << 7) + e2l] * y0b;
        m1[w0] += d[0] * c1; m1[w0 + 1] += d[1] * c1;
        m2[w0] += d[2] * c2; m2[w0 + 1] += d[3] * c2;
    }
    // W2: nc 128..191, coef x1s*y0 -> g (msg[32..47])
    for (int nc = 128; nc < 192; nc++) {
        gemm_chunk(bbase + nc * 256, aHi, aLo, d);
        int m = nc - 128, u = m >> 1, w0 = 32 + ((m & 1) << 3) + w2t;
        float c1 = sm[OF_X1S + (u << 7) + e1l] * y0a;
        float c2 = sm[OF_X1S + (u << 7) + e2l] * y0b;
        m1[w0] += d[0] * c1; m1[w0 + 1] += d[1] * c1;
        m2[w0] += d[2] * c2; m2[w0 + 1] += d[3] * c2;
    }
    // W3: nc 192..255, coef vd -> s (msg[0..31])
    for (int nc = 192; nc < 256; nc++) {
        gemm_chunk(bbase + nc * 256, aHi, aLo, d);
        int m = nc - 192, u = m >> 2, w0 = ((m & 3) << 3) + w2t;
        float c1 = sm[OF_VD + (u << 7) + e1l];
        float c2 = sm[OF_VD + (u << 7) + e2l];
        m1[w0] += d[0] * c1; m1[w0 + 1] += d[1] * c1;
        m2[w0] += d[2] * c2; m2[w0 + 1] += d[3] * c2;
    }
    // W4: nc 256..287, coef vd -> g (msg[32..47])
    for (int nc = 256; nc < 288; nc++) {
        gemm_chunk(bbase + nc * 256, aHi, aLo, d);
        int m = nc - 256, u = m >> 1, w0 = 32 + ((m & 1) << 3) + w2t;
        float c1 = sm[OF_VD + (u << 7) + e1l];
        float c2 = sm[OF_VD + (u << 7) + e2l];
        m1[w0] += d[0] * c1; m1[w0 + 1] += d[1] * c1;
        m2[w0] += d[2] * c2; m2[w0 + 1] += d[3] * c2;
    }
    // W5: nc 288..351, coef x1s (y1 deferred to scatter) -> t5 (msg[96..111])
    for (int nc = 288; nc < 352; nc++) {
        gemm_chunk(bbase + nc * 256, aHi, aLo, d);
        int m = nc - 288, u = m >> 1, w0 = 96 + ((m & 1) << 3) + w2t;
        float c1 = sm[OF_X1S + (u << 7) + e1l];
        float c2 = sm[OF_X1S + (u << 7) + e2l];
        m1[w0] += d[0] * c1; m1[w0 + 1] += d[1] * c1;
        m2[w0] += d[2] * c2; m2[w0 + 1] += d[3] * c2;
    }
    // W6: nc 352..383, coef x1v[k]*y0 -> v (msg[48 + 3w + k])
    for (int nc = 352; nc < 384; nc++) {
        gemm_chunk(bbase + nc * 256, aHi, aLo, d);
        int m = nc - 352, u = m >> 1, wl = ((m & 1) << 3) + w2t;
#pragma unroll
        for (int k = 0; k < 3; k++) {
            float c1 = sm[OF_C6 + ((k * 16 + u) << 7) + e1l];
            float c2 = sm[OF_C6 + ((k * 16 + u) << 7) + e2l];
            m1[48 + 3 * wl + k] += d[0] * c1;
            m1[48 + 3 * (wl + 1) + k] += d[1] * c1;
            m2[48 + 3 * wl + k] += d[2] * c2;
            m2[48 + 3 * (wl + 1) + k] += d[3] * c2;
        }
    }

    // ---- scatter (apply deferred W5 x y1, scale, atomics) ----
    __syncthreads();
    const float N0E = 0.14433756729740643f;   // 1/sqrt(48)
    for (int i = tid; i < 128 * 96; i += 256) {
        int e = i / 96, w = i - e * 96;
        float val = sm[OF_MSG + e * MROW + w];
        if (w >= 48) {
            int mm = w - 48, wv = mm / 3, k = mm - wv * 3;
            val += sm[OF_MSG + e * MROW + 96 + wv] * sm[OF_Y1 + (k << 7) + e];
        }
        if (eb0 + e < NE)
            atomicAdd(&g_sum[(size_t)s_dst[e] * 96 + w], val * N0E);
    }
    if (tid < 128 && eb0 + tid < NE) atomicAdd(&g_cnt[s_dst[tid]], 1.0f);
}

// ---------------- kernel: node finalize ----------------
__global__ void eq_node_kernel(const float* __restrict__ x, float* __restrict__ out) {
    int n = blockIdx.x * 256 + threadIdx.x;
    if (n >= NN) return;
    const float SQRT2 = 1.4142135623730951f;
    float inv = 1.0f / fmaxf(g_cnt[n], 1.0f);
    const float* s = g_sum + (size_t)n * 96;
    const float* xr = x + (size_t)n * 80;
    float* o = out + (size_t)n * 80;
    float gg[16];
#pragma unroll
    for (int w = 0; w < 16; w++) gg[w] = SQRT2 * fmaxf(s[32 + w] * inv, 0.0f);
#pragma unroll
    for (int w = 0; w < 32; w++) o[w] = xr[w] + SQRT2 * fmaxf(s[w] * inv, 0.0f);
#pragma unroll
    for (int w = 0; w < 16; w++)
#pragma unroll
        for (int k = 0; k < 3; k++)
            o[32 + w * 3 + k] = xr[32 + w * 3 + k] + s[48 + w * 3 + k] * inv * gg[w];
}

// ---------------- launch ----------------
extern "C" void kernel_launch(void* const* d_in, const int* in_sizes, int n_in,
                              void* d_out, int out_size) {
    const float* x  = (const float*)d_in[0];
    const float* ea = (const float*)d_in[1];
    const float* Yj = (const float*)d_in[2];
    const int*   ei = (const int*)d_in[3];
    const float* wm = (const float*)d_in[4];
    float* out = (float*)d_out;

    cudaFuncSetAttribute(eq_edge_kernel, cudaFuncAttributeMaxDynamicSharedMemorySize, SMEM_BYTES);

    eq_zero_kernel<<<(NN * 96 + 255) / 256, 256>>>();
    eq_prep_kernel<<<(3072 * 64 + 255) / 256, 256>>>(wm);
    eq_edge_kernel<<<NBLK, 256, SMEM_BYTES>>>(x, ea, Yj, ei);
    eq_node_kernel<<<(NN + 255) / 256, 256>>>(x, out);
}

// round 14
// speedup vs baseline: 1.4032x; 1.4032x over previous
#include <cuda_runtime.h>
#include <cstdint>

#define NN 12000
#define NE 120000

// ---------------- device scratch (allocation-free) ----------------
static __device__ float g_sum[NN * 96];
static __device__ float g_cnt[NN];
static __device__ float g_S[NN * 192];     // per-dst summed coefficients
static __device__ float g_M[NN * 256];     // per-src message matrix (vs Ye basis)

typedef unsigned long long ull;

// ---------------- f32x2 helpers ----------------
__device__ __forceinline__ ull packdup(float x) {
    ull r; asm("mov.b64 %0, {%1, %1};" : "=l"(r) : "f"(x)); return r;
}
__device__ __forceinline__ void fma2(ull& a, ull b, ull c) {
    asm("fma.rn.f32x2 %0, %1, %2, %0;" : "+l"(a) : "l"(b), "l"(c));
}
__device__ __forceinline__ ull mul2(ull a, ull b) {
    ull r; asm("mul.rn.f32x2 %0, %1, %2;" : "=l"(r) : "l"(a), "l"(b)); return r;
}
__device__ __forceinline__ ull add2(ull a, ull b) {
    ull r; asm("add.rn.f32x2 %0, %1, %2;" : "=l"(r) : "l"(a), "l"(b)); return r;
}
__device__ __forceinline__ float2 unpk(ull v) {
    float2 f; asm("mov.b64 {%0, %1}, %2;" : "=f"(f.x), "=f"(f.y) : "l"(v)); return f;
}

// ---------------- kernel 0: zero scratch ----------------
__global__ void eq_zero_kernel() {
    int i = blockIdx.x * 256 + threadIdx.x;
    if (i < NN * 96) g_sum[i] = 0.0f;
    if (i < NN * 192) g_S[i] = 0.0f;
    if (i < NN) g_cnt[i] = 0.0f;
}

// ================= K1: build per-node M from src-rows of w_emb =================
// 128 nodes/block. smem: s_xs[32][128]@0, s_xv[48][128]@4096 ((k*16+u)*128+n),
// s_M[128][256]@10240, s_ch[32][132]@43008. total 47232 f.
__global__ __launch_bounds__(256, 1) void eq_prepM_kernel(
    const float* __restrict__ x, const float* __restrict__ wm)
{
    extern __shared__ float sm[];
    float* s_xs = sm;
    float* s_xv = sm + 4096;
    float* s_M  = sm + 10240;
    float* s_ch = sm + 43008;
    const int tid = threadIdx.x;
    const int n0 = blockIdx.x * 128;

    for (int i = tid; i < 128 * 256; i += 256) s_M[i] = 0.0f;
    if (tid < 128) {
        int n = n0 + tid;
        bool v = n < NN;
        const float* xr = x + (size_t)n * 80;
#pragma unroll
        for (int k = 0; k < 32; k++) s_xs[k * 128 + tid] = v ? xr[k] : 0.0f;
#pragma unroll
        for (int u = 0; u < 16; u++)
#pragma unroll
            for (int k = 0; k < 3; k++)
                s_xv[(k * 16 + u) * 128 + tid] = v ? xr[32 + u * 3 + k] : 0.0f;
    }
    __syncthreads();

    const float RS = 0.08838834764831845f;       // 1/sqrt(128)
    const float INV3 = 0.57735026918962576f;     // 1/sqrt(3)

    for (int ch = 0; ch < 24; ch++) {
        {   // load chunk: wm rows 32..63 (src rows), cols ch*128.., scaled by RS
            int r = tid >> 3, cc = (tid & 7) * 16;
            const float* src = wm + (size_t)(32 + r) * 3072 + ch * 128 + cc;
            float* dstp = s_ch + r * 132 + cc;
#pragma unroll
            for (int i = 0; i < 4; i++) {
                float4 v = *(const float4*)(src + i * 4);
                dstp[i * 4 + 0] = v.x * RS; dstp[i * 4 + 1] = v.y * RS;
                dstp[i * 4 + 2] = v.z * RS; dstp[i * 4 + 3] = v.w * RS;
            }
        }
        __syncthreads();

        if (ch < 8 || (ch >= 12 && ch < 16)) {
            // W=32 blocks (W1, W3): 32 w x 4 u_local; 8 groups x 16 nodes
            const int w = tid & 31, gbase = (tid >> 5) * 16;
            float ps[16][4];
#pragma unroll
            for (int nn = 0; nn < 16; nn++)
#pragma unroll
                for (int ul = 0; ul < 4; ul++) ps[nn][ul] = 0.0f;
            for (int k = 0; k < 32; k++) {
                float cv0 = s_ch[k * 132 + w], cv1 = s_ch[k * 132 + 32 + w];
                float cv2 = s_ch[k * 132 + 64 + w], cv3 = s_ch[k * 132 + 96 + w];
                const float4* xp = (const float4*)(s_xs + k * 128 + gbase);
#pragma unroll
                for (int q = 0; q < 4; q++) {
                    float4 xv4 = xp[q];
                    float xa[4] = {xv4.x, xv4.y, xv4.z, xv4.w};
#pragma unroll
                    for (int b = 0; b < 4; b++) {
                        int nn = q * 4 + b;
                        ps[nn][0] += xa[b] * cv0; ps[nn][1] += xa[b] * cv1;
                        ps[nn][2] += xa[b] * cv2; ps[nn][3] += xa[b] * cv3;
                    }
                }
            }
            if (ch < 8) {       // W1 -> s0[w]
#pragma unroll
                for (int nn = 0; nn < 16; nn++) {
                    int n = gbase + nn; float acc = 0.0f;
#pragma unroll
                    for (int ul = 0; ul < 4; ul++)
                        acc += s_xs[(ch * 4 + ul) * 128 + n] * ps[nn][ul];
                    s_M[n * 256 + w] += acc;
                }
            } else {            // W3 -> s_j[w]
#pragma unroll
                for (int nn = 0; nn < 16; nn++) {
                    int n = gbase + nn; float a0 = 0, a1 = 0, a2 = 0;
#pragma unroll
                    for (int ul = 0; ul < 4; ul++) {
                        int u = (ch - 12) * 4 + ul; float p = ps[nn][ul];
                        a0 += s_xv[(0 * 16 + u) * 128 + n] * p;
                        a1 += s_xv[(1 * 16 + u) * 128 + n] * p;
                        a2 += s_xv[(2 * 16 + u) * 128 + n] * p;
                    }
                    s_M[n * 256 + 96 + w]  += a0 * INV3;
                    s_M[n * 256 + 128 + w] += a1 * INV3;
                    s_M[n * 256 + 160 + w] += a2 * INV3;
                }
            }
        } else {
            // W=16 blocks: 16 w x 8 u_local; 16 groups x 8 nodes
            const int w = tid & 15, gbase = (tid >> 4) * 8;
            float ps[8][8];
#pragma unroll
            for (int nn = 0; nn < 8; nn++)
#pragma unroll
                for (int ul = 0; ul < 8; ul++) ps[nn][ul] = 0.0f;
            for (int k = 0; k < 32; k++) {
                float cv[8];
#pragma unroll
                for (int ul = 0; ul < 8; ul++) cv[ul] = s_ch[k * 132 + ul * 16 + w];
                const float4* xp = (const float4*)(s_xs + k * 128 + gbase);
#pragma unroll
                for (int q = 0; q < 2; q++) {
                    float4 xv4 = xp[q];
                    float xa[4] = {xv4.x, xv4.y, xv4.z, xv4.w};
#pragma unroll
                    for (int b = 0; b < 4; b++) {
                        int nn = q * 4 + b;
#pragma unroll
                        for (int ul = 0; ul < 8; ul++) ps[nn][ul] += xa[b] * cv[ul];
                    }
                }
            }
            if (ch < 12) {          // W2 -> g0[w], u = (ch-8)*8+ul
#pragma unroll
                for (int nn = 0; nn < 8; nn++) {
                    int n = gbase + nn; float acc = 0.0f;
#pragma unroll
                    for (int ul = 0; ul < 8; ul++)
                        acc += s_xs[((ch - 8) * 8 + ul) * 128 + n] * ps[nn][ul];
                    s_M[n * 256 + 32 + w] += acc;
                }
            } else if (ch < 18) {   // W4 -> g_j[w], u = (ch-16)*8+ul
#pragma unroll
                for (int nn = 0; nn < 8; nn++) {
                    int n = gbase + nn; float a0 = 0, a1 = 0, a2 = 0;
#pragma unroll
                    for (int ul = 0; ul < 8; ul++) {
                        int u = (ch - 16) * 8 + ul; float p = ps[nn][ul];
                        a0 += s_xv[(0 * 16 + u) * 128 + n] * p;
                        a1 += s_xv[(1 * 16 + u) * 128 + n] * p;
                        a2 += s_xv[(2 * 16 + u) * 128 + n] * p;
                    }
                    s_M[n * 256 + 192 + w] += a0 * INV3;
                    s_M[n * 256 + 208 + w] += a1 * INV3;
                    s_M[n * 256 + 224 + w] += a2 * INV3;
                }
            } else if (ch < 22) {   // W5 -> t5[w], u = (ch-18)*8+ul
#pragma unroll
                for (int nn = 0; nn < 8; nn++) {
                    int n = gbase + nn; float acc = 0.0f;
#pragma unroll
                    for (int ul = 0; ul < 8; ul++)
                        acc += s_xs[((ch - 18) * 8 + ul) * 128 + n] * ps[nn][ul];
                    s_M[n * 256 + 240 + w] += acc;
                }
            } else {                // W6 -> v0[w,k], u = (ch-22)*8+ul
#pragma unroll
                for (int nn = 0; nn < 8; nn++) {
                    int n = gbase + nn; float a0 = 0, a1 = 0, a2 = 0;
#pragma unroll
                    for (int ul = 0; ul < 8; ul++) {
                        int u = (ch - 22) * 8 + ul; float p = ps[nn][ul];
                        a0 += s_xv[(0 * 16 + u) * 128 + n] * p;
                        a1 += s_xv[(1 * 16 + u) * 128 + n] * p;
                        a2 += s_xv[(2 * 16 + u) * 128 + n] * p;
                    }
                    s_M[n * 256 + 48 + 3 * w + 0] += a0;
                    s_M[n * 256 + 48 + 3 * w + 1] += a1;
                    s_M[n * 256 + 48 + 3 * w + 2] += a2;
                }
            }
        }
        __syncthreads();
    }

    for (int i = tid; i < 128 * 256; i += 256) {
        int n = n0 + (i >> 8);
        if (n < NN) g_M[(size_t)n * 256 + (i & 255)] = s_M[i];
    }
}

// ================= K2: edge kernel (ea-GEMM K=64 + termB + S atomics) =================
// 64 edges / block, 256 threads, 24 passes of 128 cols, lane owns 4 consecutive cols.
// smem floats:
//   s_emb [64][64] @0, s_msg [64][96] @4096, s_sy0 [32][64] @10240,
//   s_vd [16][64] @12288, s_x1s [32][64] @13312, s_c6 [48][64] @15360,
//   s_y1 [64*4] @18432, s_y0 [64] @18688, dst @18752, src @18816.  total 18880 f
__global__ __launch_bounds__(256, 2) void eq_edge_kernel(
    const float* __restrict__ x, const float* __restrict__ ea,
    const float* __restrict__ Yij, const int* __restrict__ eidx,
    const float* __restrict__ wm)
{
    extern __shared__ float sm[];
    float* s_emb = sm;
    float* s_msg = sm + 4096;
    float* s_sy0 = sm + 10240;
    float* s_vd  = sm + 12288;
    float* s_x1s = sm + 13312;
    float* s_c6  = sm + 15360;
    float* s_y1  = sm + 18432;
    float* s_y0  = sm + 18688;
    int* s_dst = (int*)(sm + 18752);
    int* s_src = (int*)(sm + 18816);

    const int tid = threadIdx.x;
    const int eb0 = blockIdx.x << 6;

    if (tid < 64) {
        s_dst[tid] = eidx[eb0 + tid];
        s_src[tid] = eidx[NE + eb0 + tid];
    }
    __syncthreads();

    // ---- emb staging: edge_attr only (k=0..63), scaled by 1/sqrt(128) ----
    {
        const int el = tid & 63, part = tid >> 6;   // 4 parts x 16 k
        const float RS = 0.08838834764831845f;
        const float* src = ea + (size_t)(eb0 + el) * 64 + part * 16;
        const int kb = part * 16;
#pragma unroll
        for (int i = 0; i < 4; i++) {
            float4 v = *(const float4*)(src + i * 4);
            s_emb[(kb + i * 4 + 0) * 64 + el] = v.x * RS;
            s_emb[(kb + i * 4 + 1) * 64 + el] = v.y * RS;
            s_emb[(kb + i * 4 + 2) * 64 + el] = v.z * RS;
            s_emb[(kb + i * 4 + 3) * 64 + el] = v.w * RS;
        }
    }
    // ---- per-edge coefficients ----
    if (tid < 64) {
        const int e = tid;
        float4 Y = *(const float4*)(Yij + (size_t)(eb0 + e) * 4);
        s_y0[e] = Y.x;
        s_y1[e * 4 + 0] = Y.y; s_y1[e * 4 + 1] = Y.z; s_y1[e * 4 + 2] = Y.w;
        const float* xr = x + (size_t)s_src[e] * 80;
        const float INV3 = 0.57735026918962576f;
#pragma unroll
        for (int u = 0; u < 32; u++) {
            float xs = xr[u];
            s_x1s[u * 64 + e] = xs;
            s_sy0[u * 64 + e] = xs * Y.x;
        }
#pragma unroll
        for (int u = 0; u < 16; u++) {
            float v0 = xr[32 + u * 3], v1 = xr[33 + u * 3], v2 = xr[34 + u * 3];
            s_vd[u * 64 + e] = (v0 * Y.y + v1 * Y.z + v2 * Y.w) * INV3;
            s_c6[(u)      * 64 + e] = v0 * Y.x;
            s_c6[(16 + u) * 64 + e] = v1 * Y.x;
            s_c6[(32 + u) * 64 + e] = v2 * Y.x;
        }
    }
    __syncthreads();

    // ---- term B: s_msg = M[src] applied to Ye (initializes s_msg) ----
    for (int i = tid; i < 64 * 96; i += 256) {
        int e = i / 96, w = i - e * 96;
        const float* Mr = g_M + (size_t)s_src[e] * 256;
        float y0 = s_y0[e];
        float ya = s_y1[e * 4 + 0], yb = s_y1[e * 4 + 1], yc = s_y1[e * 4 + 2];
        float val;
        if (w < 32) {
            val = y0 * Mr[w] + ya * Mr[96 + w] + yb * Mr[128 + w] + yc * Mr[160 + w];
        } else if (w < 48) {
            int wg = w - 32;
            val = y0 * Mr[32 + wg] + ya * Mr[192 + wg] + yb * Mr[208 + wg] + yc * Mr[224 + wg];
        } else {
            int m = w - 48, wv = m / 3, k = m - wv * 3;
            val = y0 * Mr[48 + m] + s_y1[e * 4 + k] * Mr[240 + wv];
        }
        s_msg[e * 96 + w] = val;
    }
    __syncthreads();

    const int ct = tid & 31;
    const int e0 = (tid >> 5) << 3;

    ull acc[4][4], macc[4][4];
#pragma unroll
    for (int p = 0; p < 4; p++)
#pragma unroll
        for (int j = 0; j < 4; j++) macc[p][j] = 0ull;

    const float* wbase = wm + (size_t)64 * 3072 + ct * 4;

    for (int pass = 0; pass < 24; ++pass) {
#pragma unroll
        for (int p = 0; p < 4; p++)
#pragma unroll
            for (int j = 0; j < 4; j++) acc[p][j] = 0ull;

        const float* wp = wbase + pass * 128;
#pragma unroll 4
        for (int c = 0; c < 64; ++c) {
            float4 wv = *(const float4*)(wp + (size_t)c * 3072);
            ull w0 = packdup(wv.x), w1 = packdup(wv.y), w2 = packdup(wv.z), w3 = packdup(wv.w);
            const ull* ep = (const ull*)(s_emb + (c << 6) + e0);
            ull q0 = ep[0], q1 = ep[1], q2 = ep[2], q3 = ep[3];
            fma2(acc[0][0], q0, w0); fma2(acc[0][1], q0, w1); fma2(acc[0][2], q0, w2); fma2(acc[0][3], q0, w3);
            fma2(acc[1][0], q1, w0); fma2(acc[1][1], q1, w1); fma2(acc[1][2], q1, w2); fma2(acc[1][3], q1, w3);
            fma2(acc[2][0], q2, w0); fma2(acc[2][1], q2, w1); fma2(acc[2][2], q2, w2); fma2(acc[2][3], q2, w3);
            fma2(acc[3][0], q3, w0); fma2(acc[3][1], q3, w1); fma2(acc[3][2], q3, w2); fma2(acc[3][3], q3, w3);
        }

        if (pass < 8) {               // W1
            int u = pass * 4 + (ct >> 3);
            const ull* cp = (const ull*)(s_sy0 + (u << 6) + e0);
#pragma unroll
            for (int p = 0; p < 4; p++) { ull c2 = cp[p];
#pragma unroll
                for (int j = 0; j < 4; j++) fma2(macc[p][j], c2, acc[p][j]); }
            if (pass == 7) {
#pragma unroll
                for (int p = 0; p < 4; p++)
#pragma unroll
                    for (int j = 0; j < 4; j++) {
                        ull v = macc[p][j];
                        v = add2(v, __shfl_xor_sync(0xffffffffu, v, 8));
                        v = add2(v, __shfl_xor_sync(0xffffffffu, v, 16));
                        if (ct < 8) {
                            float2 f = unpk(v);
                            int w = ct * 4 + j;
                            s_msg[(e0 + 2 * p) * 96 + w] += f.x;
                            s_msg[(e0 + 2 * p + 1) * 96 + w] += f.y;
                        }
                        macc[p][j] = 0ull;
                    }
            }
        } else if (pass < 12) {       // W2
            int u = (pass - 8) * 8 + (ct >> 2);
            const ull* cp = (const ull*)(s_sy0 + (u << 6) + e0);
#pragma unroll
            for (int p = 0; p < 4; p++) { ull c2 = cp[p];
#pragma unroll
                for (int j = 0; j < 4; j++) fma2(macc[p][j], c2, acc[p][j]); }
            if (pass == 11) {
#pragma unroll
                for (int p = 0; p < 4; p++)
#pragma unroll
                    for (int j = 0; j < 4; j++) {
                        ull v = macc[p][j];
                        v = add2(v, __shfl_xor_sync(0xffffffffu, v, 4));
                        v = add2(v, __shfl_xor_sync(0xffffffffu, v, 8));
                        v = add2(v, __shfl_xor_sync(0xffffffffu, v, 16));
                        if (ct < 4) {
                            float2 f = unpk(v);
                            int w = 32 + ct * 4 + j;
                            s_msg[(e0 + 2 * p) * 96 + w] += f.x;
                            s_msg[(e0 + 2 * p + 1) * 96 + w] += f.y;
                        }
                        macc[p][j] = 0ull;
                    }
            }
        } else if (pass < 16) {       // W3
            int u = (pass - 12) * 4 + (ct >> 3);
            const ull* cp = (const ull*)(s_vd + (u << 6) + e0);
#pragma unroll
            for (int p = 0; p < 4; p++) { ull c2 = cp[p];
#pragma unroll
                for (int j = 0; j < 4; j++) fma2(macc[p][j], c2, acc[p][j]); }
            if (pass == 15) {
#pragma unroll
                for (int p = 0; p < 4; p++)
#pragma unroll
                    for (int j = 0; j < 4; j++) {
                        ull v = macc[p][j];
                        v = add2(v, __shfl_xor_sync(0xffffffffu, v, 8));
                        v = add2(v, __shfl_xor_sync(0xffffffffu, v, 16));
                        if (ct < 8) {
                            float2 f = unpk(v);
                            int w = ct * 4 + j;
                            s_msg[(e0 + 2 * p) * 96 + w] += f.x;
                            s_msg[(e0 + 2 * p + 1) * 96 + w] += f.y;
                        }
                        macc[p][j] = 0ull;
                    }
            }
        } else if (pass < 18) {       // W4
            int u = (pass - 16) * 8 + (ct >> 2);
            const ull* cp = (const ull*)(s_vd + (u << 6) + e0);
#pragma unroll
            for (int p = 0; p < 4; p++) { ull c2 = cp[p];
#pragma unroll
                for (int j = 0; j < 4; j++) fma2(macc[p][j], c2, acc[p][j]); }
            if (pass == 17) {
#pragma unroll
                for (int p = 0; p < 4; p++)
#pragma unroll
                    for (int j = 0; j < 4; j++) {
                        ull v = macc[p][j];
                        v = add2(v, __shfl_xor_sync(0xffffffffu, v, 4));
                        v = add2(v, __shfl_xor_sync(0xffffffffu, v, 8));
                        v = add2(v, __shfl_xor_sync(0xffffffffu, v, 16));
                        if (ct < 4) {
                            float2 f = unpk(v);
                            int w = 32 + ct * 4 + j;
                            s_msg[(e0 + 2 * p) * 96 + w] += f.x;
                            s_msg[(e0 + 2 * p + 1) * 96 + w] += f.y;
                        }
                        macc[p][j] = 0ull;
                    }
            }
        } else if (pass < 22) {       // W5 (x y1[k])
            int u = (pass - 18) * 8 + (ct >> 2);
            const ull* cp = (const ull*)(s_x1s + (u << 6) + e0);
#pragma unroll
            for (int p = 0; p < 4; p++) { ull c2 = cp[p];
#pragma unroll
                for (int j = 0; j < 4; j++) fma2(macc[p][j], c2, acc[p][j]); }
            if (pass == 21) {
#pragma unroll
                for (int p = 0; p < 4; p++)
#pragma unroll
                    for (int j = 0; j < 4; j++) {
                        ull v = macc[p][j];
                        v = add2(v, __shfl_xor_sync(0xffffffffu, v, 4));
                        v = add2(v, __shfl_xor_sync(0xffffffffu, v, 8));
                        v = add2(v, __shfl_xor_sync(0xffffffffu, v, 16));
                        if (ct < 4) {
                            float2 f = unpk(v);
                            int w = ct * 4 + j;
                            int ex = e0 + 2 * p;
#pragma unroll
                            for (int k = 0; k < 3; k++) {
                                s_msg[ex * 96 + 48 + w * 3 + k] += f.x * s_y1[ex * 4 + k];
                                s_msg[(ex + 1) * 96 + 48 + w * 3 + k] += f.y * s_y1[(ex + 1) * 4 + k];
                            }
                        }
                        macc[p][j] = 0ull;
                    }
            }
        } else {                      // W6
            int u = (pass - 22) * 8 + (ct >> 2);
#pragma unroll
            for (int k = 0; k < 3; k++) {
                const ull* cp = (const ull*)(s_c6 + ((k * 16 + u) << 6) + e0);
#pragma unroll
                for (int p = 0; p < 4; p++) {
                    ull c2 = cp[p];
#pragma unroll
                    for (int j = 0; j < 4; j++) {
                        ull v = mul2(acc[p][j], c2);
                        v = add2(v, __shfl_xor_sync(0xffffffffu, v, 4));
                        v = add2(v, __shfl_xor_sync(0xffffffffu, v, 8));
                        v = add2(v, __shfl_xor_sync(0xffffffffu, v, 16));
                        if (ct < 4) {
                            float2 f = unpk(v);
                            int w = ct * 4 + j;
                            s_msg[(e0 + 2 * p) * 96 + 48 + w * 3 + k] += f.x;
                            s_msg[(e0 + 2 * p + 1) * 96 + 48 + w * 3 + k] += f.y;
                        }
                    }
                }
            }
        }
    }

    // ---- scatter: messages (terms B+C), coef sums S, counts ----
    __syncthreads();
    const float N0E = 0.14433756729740643f;   // 1/sqrt(48)
    for (int i = tid; i < 64 * 96; i += 256) {
        int e = i / 96, w = i - e * 96;
        atomicAdd(&g_sum[(size_t)s_dst[e] * 96 + w], s_msg[i] * N0E);
    }
    for (int i = tid; i < 64 * 192; i += 256) {
        int e = i / 192, q = i - e * 192;
        float val;
        if (q < 32) val = s_sy0[q * 64 + e];
        else if (q < 48) val = s_vd[(q - 32) * 64 + e];
        else if (q < 144) {
            int m = q - 48, u = m / 3, k = m - u * 3;
            val = s_x1s[u * 64 + e] * s_y1[e * 4 + k];
        } else val = s_c6[(q - 144) * 64 + e];
        atomicAdd(&g_S[(size_t)s_dst[e] * 192 + q], val);
    }
    if (tid < 64) atomicAdd(&g_cnt[s_dst[tid]], 1.0f);
}

// ================= K3: dst-term contraction + finalize =================
// smem: s_xs[32][128]@0, s_S[128][192]@4096, s_out[128][96]@28672, s_ch[32][132]@40960
__global__ __launch_bounds__(256, 1) void eq_node_kernel(
    const float* __restrict__ x, const float* __restrict__ wm, float* __restrict__ out)
{
    extern __shared__ float sm[];
    float* s_xs  = sm;
    float* s_S   = sm + 4096;
    float* s_out = sm + 28672;
    float* s_ch  = sm + 40960;
    const int tid = threadIdx.x;
    const int n0 = blockIdx.x * 128;

    for (int i = tid; i < 128 * 96; i += 256) s_out[i] = 0.0f;
    for (int i = tid; i < 128 * 192; i += 256) {
        int n = n0 + (i / 192);
        s_S[i] = (n < NN) ? g_S[(size_t)n * 192 + (i % 192)] : 0.0f;
    }
    if (tid < 128) {
        int n = n0 + tid;
        bool v = n < NN;
        const float* xr = x + (size_t)n * 80;
#pragma unroll
        for (int k = 0; k < 32; k++) s_xs[k * 128 + tid] = v ? xr[k] : 0.0f;
    }
    __syncthreads();

    const float RS = 0.08838834764831845f;

    for (int ch = 0; ch < 24; ch++) {
        {   // load chunk: wm rows 0..31 (dst rows)
            int r = tid >> 3, cc = (tid & 7) * 16;
            const float* src = wm + (size_t)r * 3072 + ch * 128 + cc;
            float* dstp = s_ch + r * 132 + cc;
#pragma unroll
            for (int i = 0; i < 4; i++) {
                float4 v = *(const float4*)(src + i * 4);
                dstp[i * 4 + 0] = v.x * RS; dstp[i * 4 + 1] = v.y * RS;
                dstp[i * 4 + 2] = v.z * RS; dstp[i * 4 + 3] = v.w * RS;
            }
        }
        __syncthreads();

        if (ch < 8 || (ch >= 12 && ch < 16)) {
            const int w = tid & 31, gbase = (tid >> 5) * 16;
            float ps[16][4];
#pragma unroll
            for (int nn = 0; nn < 16; nn++)
#pragma unroll
                for (int ul = 0; ul < 4; ul++) ps[nn][ul] = 0.0f;
            for (int k = 0; k < 32; k++) {
                float cv0 = s_ch[k * 132 + w], cv1 = s_ch[k * 132 + 32 + w];
                float cv2 = s_ch[k * 132 + 64 + w], cv3 = s_ch[k * 132 + 96 + w];
                const float4* xp = (const float4*)(s_xs + k * 128 + gbase);
#pragma unroll
                for (int q = 0; q < 4; q++) {
                    float4 xv4 = xp[q];
                    float xa[4] = {xv4.x, xv4.y, xv4.z, xv4.w};
#pragma unroll
                    for (int b = 0; b < 4; b++) {
                        int nn = q * 4 + b;
                        ps[nn][0] += xa[b] * cv0; ps[nn][1] += xa[b] * cv1;
                        ps[nn][2] += xa[b] * cv2; ps[nn][3] += xa[b] * cv3;
                    }
                }
            }
            const int ub = (ch < 8) ? ch * 4 : (ch - 12) * 4;
            const int soff = (ch < 8) ? 0 : 32;   // S_sy0 @0, S_vd @32
#pragma unroll
            for (int nn = 0; nn < 16; nn++) {
                int n = gbase + nn; float acc = 0.0f;
#pragma unroll
                for (int ul = 0; ul < 4; ul++)
                    acc += s_S[n * 192 + soff + ub + ul] * ps[nn][ul];
                s_out[n * 96 + w] += acc;   // both W1 and W3 -> s[w]
            }
        } else {
            const int w = tid & 15, gbase = (tid >> 4) * 8;
            float ps[8][8];
#pragma unroll
            for (int nn = 0; nn < 8; nn++)
#pragma unroll
                for (int ul = 0; ul < 8; ul++) ps[nn][ul] = 0.0f;
            for (int k = 0; k < 32; k++) {
                float cv[8];
#pragma unroll
                for (int ul = 0; ul < 8; ul++) cv[ul] = s_ch[k * 132 + ul * 16 + w];
                const float4* xp = (const float4*)(s_xs + k * 128 + gbase);
#pragma unroll
                for (int q = 0; q < 2; q++) {
                    float4 xv4 = xp[q];
                    float xa[4] = {xv4.x, xv4.y, xv4.z, xv4.w};
#pragma unroll
                    for (int b = 0; b < 4; b++) {
                        int nn = q * 4 + b;
#pragma unroll
                        for (int ul = 0; ul < 8; ul++) ps[nn][ul] += xa[b] * cv[ul];
                    }
                }
            }
            if (ch < 12) {          // W2 -> g[w], S_sy0
                const int ub = (ch - 8) * 8;
#pragma unroll
                for (int nn = 0; nn < 8; nn++) {
                    int n = gbase + nn; float acc = 0.0f;
#pragma unroll
                    for (int ul = 0; ul < 8; ul++)
                        acc += s_S[n * 192 + ub + ul] * ps[nn][ul];
                    s_out[n * 96 + 32 + w] += acc;
                }
            } else if (ch < 18) {   // W4 -> g[w], S_vd
                const int ub = (ch - 16) * 8;
#pragma unroll
                for (int nn = 0; nn < 8; nn++) {
                    int n = gbase + nn; float acc = 0.0f;
#pragma unroll
                    for (int ul = 0; ul < 8; ul++)
                        acc += s_S[n * 192 + 32 + ub + ul] * ps[nn][ul];
                    s_out[n * 96 + 32 + w] += acc;
                }
            } else if (ch < 22) {   // W5 -> v[w,k], S_w5 @48 + u*3+k
                const int ub = (ch - 18) * 8;
#pragma unroll
                for (int nn = 0; nn < 8; nn++) {
                    int n = gbase + nn; float a0 = 0, a1 = 0, a2 = 0;
#pragma unroll
                    for (int ul = 0; ul < 8; ul++) {
                        float p = ps[nn][ul];
                        const float* sp = s_S + n * 192 + 48 + (ub + ul) * 3;
                        a0 += sp[0] * p; a1 += sp[1] * p; a2 += sp[2] * p;
                    }
                    s_out[n * 96 + 48 + 3 * w + 0] += a0;
                    s_out[n * 96 + 48 + 3 * w + 1] += a1;
                    s_out[n * 96 + 48 + 3 * w + 2] += a2;
                }
            } else {                // W6 -> v[w,k], S_c6 @144 + k*16+u
                const int ub = (ch - 22) * 8;
#pragma unroll
                for (int nn = 0; nn < 8; nn++) {
                    int n = gbase + nn; float a0 = 0, a1 = 0, a2 = 0;
#pragma unroll
                    for (int ul = 0; ul < 8; ul++) {
                        float p = ps[nn][ul];
                        int u = ub + ul;
                        a0 += s_S[n * 192 + 144 + 0 * 16 + u] * p;
                        a1 += s_S[n * 192 + 144 + 1 * 16 + u] * p;
                        a2 += s_S[n * 192 + 144 + 2 * 16 + u] * p;
                    }
                    s_out[n * 96 + 48 + 3 * w + 0] += a0;
                    s_out[n * 96 + 48 + 3 * w + 1] += a1;
                    s_out[n * 96 + 48 + 3 * w + 2] += a2;
                }
            }
        }
        __syncthreads();
    }

    // ---- finalize ----
    if (tid < 128) {
        int n = n0 + tid;
        if (n < NN) {
            const float SQRT2 = 1.4142135623730951f;
            const float N0E = 0.14433756729740643f;
            float inv = 1.0f / fmaxf(g_cnt[n], 1.0f);
            const float* gs = g_sum + (size_t)n * 96;
            const float* so = s_out + tid * 96;
            const float* xr = x + (size_t)n * 80;
            float* o = out + (size_t)n * 80;
            float gg[16];
#pragma unroll
            for (int w = 0; w < 16; w++)
                gg[w] = SQRT2 * fmaxf((gs[32 + w] + N0E * so[32 + w]) * inv, 0.0f);
#pragma unroll
            for (int w = 0; w < 32; w++)
                o[w] = xr[w] + SQRT2 * fmaxf((gs[w] + N0E * so[w]) * inv, 0.0f);
#pragma unroll
            for (int w = 0; w < 16; w++)
#pragma unroll
                for (int k = 0; k < 3; k++)
                    o[32 + w * 3 + k] = xr[32 + w * 3 + k] +
                        (gs[48 + w * 3 + k] + N0E * so[48 + w * 3 + k]) * inv * gg[w];
        }
    }
}

// ---------------- launch ----------------
extern "C" void kernel_launch(void* const* d_in, const int* in_sizes, int n_in,
                              void* d_out, int out_size) {
    const float* x  = (const float*)d_in[0];
    const float* ea = (const float*)d_in[1];
    const float* Yj = (const float*)d_in[2];
    const int*   ei = (const int*)d_in[3];
    const float* wm = (const float*)d_in[4];
    float* out = (float*)d_out;

    cudaFuncSetAttribute(eq_prepM_kernel, cudaFuncAttributeMaxDynamicSharedMemorySize, 188928);
    cudaFuncSetAttribute(eq_edge_kernel,  cudaFuncAttributeMaxDynamicSharedMemorySize, 75520);
    cudaFuncSetAttribute(eq_node_kernel,  cudaFuncAttributeMaxDynamicSharedMemorySize, 180736);

    eq_zero_kernel<<<(NN * 192 + 255) / 256, 256>>>();
    eq_prepM_kernel<<<(NN + 127) / 128, 256, 188928>>>(x, wm);
    eq_edge_kernel<<<NE / 64, 256, 75520>>>(x, ea, Yj, ei, wm);
    eq_node_kernel<<<(NN + 127) / 128, 256, 180736>>>(x, wm, out);
}

// round 15
// speedup vs baseline: 1.4157x; 1.0090x over previous
#include <cuda_runtime.h>
#include <cstdint>

#define NN 12000
#define NE 120000

// ---------------- device scratch (allocation-free) ----------------
static __device__ float g_sum[NN * 96];
static __device__ float g_cnt[NN];
static __device__ float g_S[NN * 192];     // per-dst summed coefficients
static __device__ float g_M[NN * 256];     // per-src message matrix (vs Ye basis)

typedef unsigned long long ull;

// ---------------- f32x2 helpers ----------------
__device__ __forceinline__ ull packdup(float x) {
    ull r; asm("mov.b64 %0, {%1, %1};" : "=l"(r) : "f"(x)); return r;
}
__device__ __forceinline__ void fma2(ull& a, ull b, ull c) {
    asm("fma.rn.f32x2 %0, %1, %2, %0;" : "+l"(a) : "l"(b), "l"(c));
}
__device__ __forceinline__ ull mul2(ull a, ull b) {
    ull r; asm("mul.rn.f32x2 %0, %1, %2;" : "=l"(r) : "l"(a), "l"(b)); return r;
}
__device__ __forceinline__ ull add2(ull a, ull b) {
    ull r; asm("add.rn.f32x2 %0, %1, %2;" : "=l"(r) : "l"(a), "l"(b)); return r;
}
__device__ __forceinline__ float2 unpk(ull v) {
    float2 f; asm("mov.b64 {%0, %1}, %2;" : "=f"(f.x), "=f"(f.y) : "l"(v)); return f;
}

// ---------------- kernel 0: zero scratch ----------------
__global__ void eq_zero_kernel() {
    int i = blockIdx.x * 256 + threadIdx.x;
    if (i < NN * 96) g_sum[i] = 0.0f;
    if (i < NN * 192) g_S[i] = 0.0f;
    if (i < NN) g_cnt[i] = 0.0f;
}

// ================= K1: build per-node M from src-rows of w_emb =================
// 64 nodes/block (188 blocks), occupancy 2. smem floats:
//   s_xs[32][64]@0 (2048), s_xv[48][64]@2048 (3072), s_M[64][256]@5120 (16384),
//   s_ch[32][132]@21504 (4224). total 25728 f = 102912 B
__global__ __launch_bounds__(256, 2) void eq_prepM_kernel(
    const float* __restrict__ x, const float* __restrict__ wm)
{
    extern __shared__ float sm[];
    float* s_xs = sm;
    float* s_xv = sm + 2048;
    float* s_M  = sm + 5120;
    float* s_ch = sm + 21504;
    const int tid = threadIdx.x;
    const int n0 = blockIdx.x * 64;

    for (int i = tid; i < 64 * 256; i += 256) s_M[i] = 0.0f;
    if (tid < 64) {
        int n = n0 + tid;
        bool v = n < NN;
        const float* xr = x + (size_t)n * 80;
#pragma unroll
        for (int k = 0; k < 32; k++) s_xs[k * 64 + tid] = v ? xr[k] : 0.0f;
#pragma unroll
        for (int u = 0; u < 16; u++)
#pragma unroll
            for (int k = 0; k < 3; k++)
                s_xv[(k * 16 + u) * 64 + tid] = v ? xr[32 + u * 3 + k] : 0.0f;
    }
    __syncthreads();

    const float RS = 0.08838834764831845f;       // 1/sqrt(128)
    const float INV3 = 0.57735026918962576f;     // 1/sqrt(3)

    for (int ch = 0; ch < 24; ch++) {
        {   // load chunk: wm rows 32..63 (src rows), cols ch*128.., scaled by RS
            int r = tid >> 3, cc = (tid & 7) * 16;
            const float* src = wm + (size_t)(32 + r) * 3072 + ch * 128 + cc;
            float* dstp = s_ch + r * 132 + cc;
#pragma unroll
            for (int i = 0; i < 4; i++) {
                float4 v = *(const float4*)(src + i * 4);
                dstp[i * 4 + 0] = v.x * RS; dstp[i * 4 + 1] = v.y * RS;
                dstp[i * 4 + 2] = v.z * RS; dstp[i * 4 + 3] = v.w * RS;
            }
        }
        __syncthreads();

        if (ch < 8 || (ch >= 12 && ch < 16)) {
            // W=32 blocks (W1, W3): 8 groups x 8 nodes, ps[8][4]
            const int w = tid & 31, gbase = (tid >> 5) * 8;
            float ps[8][4];
#pragma unroll
            for (int nn = 0; nn < 8; nn++)
#pragma unroll
                for (int ul = 0; ul < 4; ul++) ps[nn][ul] = 0.0f;
            for (int k = 0; k < 32; k++) {
                float cv0 = s_ch[k * 132 + w], cv1 = s_ch[k * 132 + 32 + w];
                float cv2 = s_ch[k * 132 + 64 + w], cv3 = s_ch[k * 132 + 96 + w];
                const float4* xp = (const float4*)(s_xs + k * 64 + gbase);
#pragma unroll
                for (int q = 0; q < 2; q++) {
                    float4 xv4 = xp[q];
                    float xa[4] = {xv4.x, xv4.y, xv4.z, xv4.w};
#pragma unroll
                    for (int b = 0; b < 4; b++) {
                        int nn = q * 4 + b;
                        ps[nn][0] += xa[b] * cv0; ps[nn][1] += xa[b] * cv1;
                        ps[nn][2] += xa[b] * cv2; ps[nn][3] += xa[b] * cv3;
                    }
                }
            }
            if (ch < 8) {       // W1 -> s0[w]
#pragma unroll
                for (int nn = 0; nn < 8; nn++) {
                    int n = gbase + nn; float acc = 0.0f;
#pragma unroll
                    for (int ul = 0; ul < 4; ul++)
                        acc += s_xs[(ch * 4 + ul) * 64 + n] * ps[nn][ul];
                    s_M[n * 256 + w] += acc;
                }
            } else {            // W3 -> s_j[w]
#pragma unroll
                for (int nn = 0; nn < 8; nn++) {
                    int n = gbase + nn; float a0 = 0, a1 = 0, a2 = 0;
#pragma unroll
                    for (int ul = 0; ul < 4; ul++) {
                        int u = (ch - 12) * 4 + ul; float p = ps[nn][ul];
                        a0 += s_xv[(0 * 16 + u) * 64 + n] * p;
                        a1 += s_xv[(1 * 16 + u) * 64 + n] * p;
                        a2 += s_xv[(2 * 16 + u) * 64 + n] * p;
                    }
                    s_M[n * 256 + 96 + w]  += a0 * INV3;
                    s_M[n * 256 + 128 + w] += a1 * INV3;
                    s_M[n * 256 + 160 + w] += a2 * INV3;
                }
            }
        } else {
            // W=16 blocks: 16 groups x 4 nodes, ps[4][8]
            const int w = tid & 15, gbase = (tid >> 4) * 4;
            float ps[4][8];
#pragma unroll
            for (int nn = 0; nn < 4; nn++)
#pragma unroll
                for (int ul = 0; ul < 8; ul++) ps[nn][ul] = 0.0f;
            for (int k = 0; k < 32; k++) {
                float cv[8];
#pragma unroll
                for (int ul = 0; ul < 8; ul++) cv[ul] = s_ch[k * 132 + ul * 16 + w];
                float4 xv4 = *(const float4*)(s_xs + k * 64 + gbase);
                float xa[4] = {xv4.x, xv4.y, xv4.z, xv4.w};
#pragma unroll
                for (int b = 0; b < 4; b++)
#pragma unroll
                    for (int ul = 0; ul < 8; ul++) ps[b][ul] += xa[b] * cv[ul];
            }
            if (ch < 12) {          // W2 -> g0[w]
#pragma unroll
                for (int nn = 0; nn < 4; nn++) {
                    int n = gbase + nn; float acc = 0.0f;
#pragma unroll
                    for (int ul = 0; ul < 8; ul++)
                        acc += s_xs[((ch - 8) * 8 + ul) * 64 + n] * ps[nn][ul];
                    s_M[n * 256 + 32 + w] += acc;
                }
            } else if (ch < 18) {   // W4 -> g_j[w]
#pragma unroll
                for (int nn = 0; nn < 4; nn++) {
                    int n = gbase + nn; float a0 = 0, a1 = 0, a2 = 0;
#pragma unroll
                    for (int ul = 0; ul < 8; ul++) {
                        int u = (ch - 16) * 8 + ul; float p = ps[nn][ul];
                        a0 += s_xv[(0 * 16 + u) * 64 + n] * p;
                        a1 += s_xv[(1 * 16 + u) * 64 + n] * p;
                        a2 += s_xv[(2 * 16 + u) * 64 + n] * p;
                    }
                    s_M[n * 256 + 192 + w] += a0 * INV3;
                    s_M[n * 256 + 208 + w] += a1 * INV3;
                    s_M[n * 256 + 224 + w] += a2 * INV3;
                }
            } else if (ch < 22) {   // W5 -> t5[w]
#pragma unroll
                for (int nn = 0; nn < 4; nn++) {
                    int n = gbase + nn; float acc = 0.0f;
#pragma unroll
                    for (int ul = 0; ul < 8; ul++)
                        acc += s_xs[((ch - 18) * 8 + ul) * 64 + n] * ps[nn][ul];
                    s_M[n * 256 + 240 + w] += acc;
                }
            } else {                // W6 -> v0[w,k]
#pragma unroll
                for (int nn = 0; nn < 4; nn++) {
                    int n = gbase + nn; float a0 = 0, a1 = 0, a2 = 0;
#pragma unroll
                    for (int ul = 0; ul < 8; ul++) {
                        int u = (ch - 22) * 8 + ul; float p = ps[nn][ul];
                        a0 += s_xv[(0 * 16 + u) * 64 + n] * p;
                        a1 += s_xv[(1 * 16 + u) * 64 + n] * p;
                        a2 += s_xv[(2 * 16 + u) * 64 + n] * p;
                    }
                    s_M[n * 256 + 48 + 3 * w + 0] += a0;
                    s_M[n * 256 + 48 + 3 * w + 1] += a1;
                    s_M[n * 256 + 48 + 3 * w + 2] += a2;
                }
            }
        }
        __syncthreads();
    }

    for (int i = tid; i < 64 * 256; i += 256) {
        int n = n0 + (i >> 8);
        if (n < NN) g_M[(size_t)n * 256 + (i & 255)] = s_M[i];
    }
}

// ================= K2: edge kernel (ea-GEMM K=64 + termB + S atomics) =================
// 64 edges / block, 256 threads, 24 passes of 128 cols, lane owns 4 consecutive cols.
__global__ __launch_bounds__(256, 2) void eq_edge_kernel(
    const float* __restrict__ x, const float* __restrict__ ea,
    const float* __restrict__ Yij, const int* __restrict__ eidx,
    const float* __restrict__ wm)
{
    extern __shared__ float sm[];
    float* s_emb = sm;
    float* s_msg = sm + 4096;
    float* s_sy0 = sm + 10240;
    float* s_vd  = sm + 12288;
    float* s_x1s = sm + 13312;
    float* s_c6  = sm + 15360;
    float* s_y1  = sm + 18432;
    float* s_y0  = sm + 18688;
    int* s_dst = (int*)(sm + 18752);
    int* s_src = (int*)(sm + 18816);

    const int tid = threadIdx.x;
    const int eb0 = blockIdx.x << 6;

    if (tid < 64) {
        s_dst[tid] = eidx[eb0 + tid];
        s_src[tid] = eidx[NE + eb0 + tid];
    }
    __syncthreads();

    // ---- emb staging: edge_attr only (k=0..63), scaled by 1/sqrt(128) ----
    {
        const int el = tid & 63, part = tid >> 6;   // 4 parts x 16 k
        const float RS = 0.08838834764831845f;
        const float* src = ea + (size_t)(eb0 + el) * 64 + part * 16;
        const int kb = part * 16;
#pragma unroll
        for (int i = 0; i < 4; i++) {
            float4 v = *(const float4*)(src + i * 4);
            s_emb[(kb + i * 4 + 0) * 64 + el] = v.x * RS;
            s_emb[(kb + i * 4 + 1) * 64 + el] = v.y * RS;
            s_emb[(kb + i * 4 + 2) * 64 + el] = v.z * RS;
            s_emb[(kb + i * 4 + 3) * 64 + el] = v.w * RS;
        }
    }
    // ---- per-edge coefficients ----
    if (tid < 64) {
        const int e = tid;
        float4 Y = *(const float4*)(Yij + (size_t)(eb0 + e) * 4);
        s_y0[e] = Y.x;
        s_y1[e * 4 + 0] = Y.y; s_y1[e * 4 + 1] = Y.z; s_y1[e * 4 + 2] = Y.w;
        const float* xr = x + (size_t)s_src[e] * 80;
        const float INV3 = 0.57735026918962576f;
#pragma unroll
        for (int u = 0; u < 32; u++) {
            float xs = xr[u];
            s_x1s[u * 64 + e] = xs;
            s_sy0[u * 64 + e] = xs * Y.x;
        }
#pragma unroll
        for (int u = 0; u < 16; u++) {
            float v0 = xr[32 + u * 3], v1 = xr[33 + u * 3], v2 = xr[34 + u * 3];
            s_vd[u * 64 + e] = (v0 * Y.y + v1 * Y.z + v2 * Y.w) * INV3;
            s_c6[(u)      * 64 + e] = v0 * Y.x;
            s_c6[(16 + u) * 64 + e] = v1 * Y.x;
            s_c6[(32 + u) * 64 + e] = v2 * Y.x;
        }
    }
    __syncthreads();

    // ---- term B: s_msg = M[src] applied to Ye ----
    for (int i = tid; i < 64 * 96; i += 256) {
        int e = i / 96, w = i - e * 96;
        const float* Mr = g_M + (size_t)s_src[e] * 256;
        float y0 = s_y0[e];
        float ya = s_y1[e * 4 + 0], yb = s_y1[e * 4 + 1], yc = s_y1[e * 4 + 2];
        float val;
        if (w < 32) {
            val = y0 * Mr[w] + ya * Mr[96 + w] + yb * Mr[128 + w] + yc * Mr[160 + w];
        } else if (w < 48) {
            int wg = w - 32;
            val = y0 * Mr[32 + wg] + ya * Mr[192 + wg] + yb * Mr[208 + wg] + yc * Mr[224 + wg];
        } else {
            int m = w - 48, wv = m / 3, k = m - wv * 3;
            val = y0 * Mr[48 + m] + s_y1[e * 4 + k] * Mr[240 + wv];
        }
        s_msg[e * 96 + w] = val;
    }
    __syncthreads();

    const int ct = tid & 31;
    const int e0 = (tid >> 5) << 3;

    ull acc[4][4], macc[4][4];
#pragma unroll
    for (int p = 0; p < 4; p++)
#pragma unroll
        for (int j = 0; j < 4; j++) macc[p][j] = 0ull;

    const float* wbase = wm + (size_t)64 * 3072 + ct * 4;

    for (int pass = 0; pass < 24; ++pass) {
#pragma unroll
        for (int p = 0; p < 4; p++)
#pragma unroll
            for (int j = 0; j < 4; j++) acc[p][j] = 0ull;

        const float* wp = wbase + pass * 128;
#pragma unroll 4
        for (int c = 0; c < 64; ++c) {
            float4 wv = *(const float4*)(wp + (size_t)c * 3072);
            ull w0 = packdup(wv.x), w1 = packdup(wv.y), w2 = packdup(wv.z), w3 = packdup(wv.w);
            const ull* ep = (const ull*)(s_emb + (c << 6) + e0);
            ull q0 = ep[0], q1 = ep[1], q2 = ep[2], q3 = ep[3];
            fma2(acc[0][0], q0, w0); fma2(acc[0][1], q0, w1); fma2(acc[0][2], q0, w2); fma2(acc[0][3], q0, w3);
            fma2(acc[1][0], q1, w0); fma2(acc[1][1], q1, w1); fma2(acc[1][2], q1, w2); fma2(acc[1][3], q1, w3);
            fma2(acc[2][0], q2, w0); fma2(acc[2][1], q2, w1); fma2(acc[2][2], q2, w2); fma2(acc[2][3], q2, w3);
            fma2(acc[3][0], q3, w0); fma2(acc[3][1], q3, w1); fma2(acc[3][2], q3, w2); fma2(acc[3][3], q3, w3);
        }

        if (pass < 8) {               // W1
            int u = pass * 4 + (ct >> 3);
            const ull* cp = (const ull*)(s_sy0 + (u << 6) + e0);
#pragma unroll
            for (int p = 0; p < 4; p++) { ull c2 = cp[p];
#pragma unroll
                for (int j = 0; j < 4; j++) fma2(macc[p][j], c2, acc[p][j]); }
            if (pass == 7) {
#pragma unroll
                for (int p = 0; p < 4; p++)
#pragma unroll
                    for (int j = 0; j < 4; j++) {
                        ull v = macc[p][j];
                        v = add2(v, __shfl_xor_sync(0xffffffffu, v, 8));
                        v = add2(v, __shfl_xor_sync(0xffffffffu, v, 16));
                        if (ct < 8) {
                            float2 f = unpk(v);
                            int w = ct * 4 + j;
                            s_msg[(e0 + 2 * p) * 96 + w] += f.x;
                            s_msg[(e0 + 2 * p + 1) * 96 + w] += f.y;
                        }
                        macc[p][j] = 0ull;
                    }
            }
        } else if (pass < 12) {       // W2
            int u = (pass - 8) * 8 + (ct >> 2);
            const ull* cp = (const ull*)(s_sy0 + (u << 6) + e0);
#pragma unroll
            for (int p = 0; p < 4; p++) { ull c2 = cp[p];
#pragma unroll
                for (int j = 0; j < 4; j++) fma2(macc[p][j], c2, acc[p][j]); }
            if (pass == 11) {
#pragma unroll
                for (int p = 0; p < 4; p++)
#pragma unroll
                    for (int j = 0; j < 4; j++) {
                        ull v = macc[p][j];
                        v = add2(v, __shfl_xor_sync(0xffffffffu, v, 4));
                        v = add2(v, __shfl_xor_sync(0xffffffffu, v, 8));
                        v = add2(v, __shfl_xor_sync(0xffffffffu, v, 16));
                        if (ct < 4) {
                            float2 f = unpk(v);
                            int w = 32 + ct * 4 + j;
                            s_msg[(e0 + 2 * p) * 96 + w] += f.x;
                            s_msg[(e0 + 2 * p + 1) * 96 + w] += f.y;
                        }
                        macc[p][j] = 0ull;
                    }
            }
        } else if (pass < 16) {       // W3
            int u = (pass - 12) * 4 + (ct >> 3);
            const ull* cp = (const ull*)(s_vd + (u << 6) + e0);
#pragma unroll
            for (int p = 0; p < 4; p++) { ull c2 = cp[p];
#pragma unroll
                for (int j = 0; j < 4; j++) fma2(macc[p][j], c2, acc[p][j]); }
            if (pass == 15) {
#pragma unroll
                for (int p = 0; p < 4; p++)
#pragma unroll
                    for (int j = 0; j < 4; j++) {
                        ull v = macc[p][j];
                        v = add2(v, __shfl_xor_sync(0xffffffffu, v, 8));
                        v = add2(v, __shfl_xor_sync(0xffffffffu, v, 16));
                        if (ct < 8) {
                            float2 f = unpk(v);
                            int w = ct * 4 + j;
                            s_msg[(e0 + 2 * p) * 96 + w] += f.x;
                            s_msg[(e0 + 2 * p + 1) * 96 + w] += f.y;
                        }
                        macc[p][j] = 0ull;
                    }
            }
        } else if (pass < 18) {       // W4
            int u = (pass - 16) * 8 + (ct >> 2);
            const ull* cp = (const ull*)(s_vd + (u << 6) + e0);
#pragma unroll
            for (int p = 0; p < 4; p++) { ull c2 = cp[p];
#pragma unroll
                for (int j = 0; j < 4; j++) fma2(macc[p][j], c2, acc[p][j]); }
            if (pass == 17) {
#pragma unroll
                for (int p = 0; p < 4; p++)
#pragma unroll
                    for (int j = 0; j < 4; j++) {
                        ull v = macc[p][j];
                        v = add2(v, __shfl_xor_sync(0xffffffffu, v, 4));
                        v = add2(v, __shfl_xor_sync(0xffffffffu, v, 8));
                        v = add2(v, __shfl_xor_sync(0xffffffffu, v, 16));
                        if (ct < 4) {
                            float2 f = unpk(v);
                            int w = 32 + ct * 4 + j;
                            s_msg[(e0 + 2 * p) * 96 + w] += f.x;
                            s_msg[(e0 + 2 * p + 1) * 96 + w] += f.y;
                        }
                        macc[p][j] = 0ull;
                    }
            }
        } else if (pass < 22) {       // W5 (x y1[k])
            int u = (pass - 18) * 8 + (ct >> 2);
            const ull* cp = (const ull*)(s_x1s + (u << 6) + e0);
#pragma unroll
            for (int p = 0; p < 4; p++) { ull c2 = cp[p];
#pragma unroll
                for (int j = 0; j < 4; j++) fma2(macc[p][j], c2, acc[p][j]); }
            if (pass == 21) {
#pragma unroll
                for (int p = 0; p < 4; p++)
#pragma unroll
                    for (int j = 0; j < 4; j++) {
                        ull v = macc[p][j];
                        v = add2(v, __shfl_xor_sync(0xffffffffu, v, 4));
                        v = add2(v, __shfl_xor_sync(0xffffffffu, v, 8));
                        v = add2(v, __shfl_xor_sync(0xffffffffu, v, 16));
                        if (ct < 4) {
                            float2 f = unpk(v);
                            int w = ct * 4 + j;
                            int ex = e0 + 2 * p;
#pragma unroll
                            for (int k = 0; k < 3; k++) {
                                s_msg[ex * 96 + 48 + w * 3 + k] += f.x * s_y1[ex * 4 + k];
                                s_msg[(ex + 1) * 96 + 48 + w * 3 + k] += f.y * s_y1[(ex + 1) * 4 + k];
                            }
                        }
                        macc[p][j] = 0ull;
                    }
            }
        } else {                      // W6
            int u = (pass - 22) * 8 + (ct >> 2);
#pragma unroll
            for (int k = 0; k < 3; k++) {
                const ull* cp = (const ull*)(s_c6 + ((k * 16 + u) << 6) + e0);
#pragma unroll
                for (int p = 0; p < 4; p++) {
                    ull c2 = cp[p];
#pragma unroll
                    for (int j = 0; j < 4; j++) {
                        ull v = mul2(acc[p][j], c2);
                        v = add2(v, __shfl_xor_sync(0xffffffffu, v, 4));
                        v = add2(v, __shfl_xor_sync(0xffffffffu, v, 8));
                        v = add2(v, __shfl_xor_sync(0xffffffffu, v, 16));
                        if (ct < 4) {
                            float2 f = unpk(v);
                            int w = ct * 4 + j;
                            s_msg[(e0 + 2 * p) * 96 + 48 + w * 3 + k] += f.x;
                            s_msg[(e0 + 2 * p + 1) * 96 + 48 + w * 3 + k] += f.y;
                        }
                    }
                }
            }
        }
    }

    // ---- scatter: messages (terms B+C), coef sums S, counts ----
    __syncthreads();
    const float N0E = 0.14433756729740643f;   // 1/sqrt(48)
    for (int i = tid; i < 64 * 96; i += 256) {
        int e = i / 96, w = i - e * 96;
        atomicAdd(&g_sum[(size_t)s_dst[e] * 96 + w], s_msg[i] * N0E);
    }
    for (int i = tid; i < 64 * 192; i += 256) {
        int e = i / 192, q = i - e * 192;
        float val;
        if (q < 32) val = s_sy0[q * 64 + e];
        else if (q < 48) val = s_vd[(q - 32) * 64 + e];
        else if (q < 144) {
            int m = q - 48, u = m / 3, k = m - u * 3;
            val = s_x1s[u * 64 + e] * s_y1[e * 4 + k];
        } else val = s_c6[(q - 144) * 64 + e];
        atomicAdd(&g_S[(size_t)s_dst[e] * 192 + q], val);
    }
    if (tid < 64) atomicAdd(&g_cnt[s_dst[tid]], 1.0f);
}

// ================= K3: dst-term contraction + finalize =================
// 64 nodes/block (188 blocks), occupancy 2. smem floats:
//   s_xs[32][64]@0 (2048), s_S[64][192]@2048 (12288), s_out[64][96]@14336 (6144),
//   s_ch[32][132]@20480 (4224). total 24704 f = 98816 B
__global__ __launch_bounds__(256, 2) void eq_node_kernel(
    const float* __restrict__ x, const float* __restrict__ wm, float* __restrict__ out)
{
    extern __shared__ float sm[];
    float* s_xs  = sm;
    float* s_S   = sm + 2048;
    float* s_out = sm + 14336;
    float* s_ch  = sm + 20480;
    const int tid = threadIdx.x;
    const int n0 = blockIdx.x * 64;

    for (int i = tid; i < 64 * 96; i += 256) s_out[i] = 0.0f;
    for (int i = tid; i < 64 * 192; i += 256) {
        int n = n0 + (i / 192);
        s_S[i] = (n < NN) ? g_S[(size_t)n * 192 + (i % 192)] : 0.0f;
    }
    if (tid < 64) {
        int n = n0 + tid;
        bool v = n < NN;
        const float* xr = x + (size_t)n * 80;
#pragma unroll
        for (int k = 0; k < 32; k++) s_xs[k * 64 + tid] = v ? xr[k] : 0.0f;
    }
    __syncthreads();

    const float RS = 0.08838834764831845f;

    for (int ch = 0; ch < 24; ch++) {
        {   // load chunk: wm rows 0..31 (dst rows)
            int r = tid >> 3, cc = (tid & 7) * 16;
            const float* src = wm + (size_t)r * 3072 + ch * 128 + cc;
            float* dstp = s_ch + r * 132 + cc;
#pragma unroll
            for (int i = 0; i < 4; i++) {
                float4 v = *(const float4*)(src + i * 4);
                dstp[i * 4 + 0] = v.x * RS; dstp[i * 4 + 1] = v.y * RS;
                dstp[i * 4 + 2] = v.z * RS; dstp[i * 4 + 3] = v.w * RS;
            }
        }
        __syncthreads();

        if (ch < 8 || (ch >= 12 && ch < 16)) {
            const int w = tid & 31, gbase = (tid >> 5) * 8;
            float ps[8][4];
#pragma unroll
            for (int nn = 0; nn < 8; nn++)
#pragma unroll
                for (int ul = 0; ul < 4; ul++) ps[nn][ul] = 0.0f;
            for (int k = 0; k < 32; k++) {
                float cv0 = s_ch[k * 132 + w], cv1 = s_ch[k * 132 + 32 + w];
                float cv2 = s_ch[k * 132 + 64 + w], cv3 = s_ch[k * 132 + 96 + w];
                const float4* xp = (const float4*)(s_xs + k * 64 + gbase);
#pragma unroll
                for (int q = 0; q < 2; q++) {
                    float4 xv4 = xp[q];
                    float xa[4] = {xv4.x, xv4.y, xv4.z, xv4.w};
#pragma unroll
                    for (int b = 0; b < 4; b++) {
                        int nn = q * 4 + b;
                        ps[nn][0] += xa[b] * cv0; ps[nn][1] += xa[b] * cv1;
                        ps[nn][2] += xa[b] * cv2; ps[nn][3] += xa[b] * cv3;
                    }
                }
            }
            const int ub = (ch < 8) ? ch * 4 : (ch - 12) * 4;
            const int soff = (ch < 8) ? 0 : 32;   // S_sy0 @0, S_vd @32
#pragma unroll
            for (int nn = 0; nn < 8; nn++) {
                int n = gbase + nn; float acc = 0.0f;
#pragma unroll
                for (int ul = 0; ul < 4; ul++)
                    acc += s_S[n * 192 + soff + ub + ul] * ps[nn][ul];
                s_out[n * 96 + w] += acc;   // both W1 and W3 -> s[w]
            }
        } else {
            const int w = tid & 15, gbase = (tid >> 4) * 4;
            float ps[4][8];
#pragma unroll
            for (int nn = 0; nn < 4; nn++)
#pragma unroll
                for (int ul = 0; ul < 8; ul++) ps[nn][ul] = 0.0f;
            for (int k = 0; k < 32; k++) {
                float cv[8];
#pragma unroll
                for (int ul = 0; ul < 8; ul++) cv[ul] = s_ch[k * 132 + ul * 16 + w];
                float4 xv4 = *(const float4*)(s_xs + k * 64 + gbase);
                float xa[4] = {xv4.x, xv4.y, xv4.z, xv4.w};
#pragma unroll
                for (int b = 0; b < 4; b++)
#pragma unroll
                    for (int ul = 0; ul < 8; ul++) ps[b][ul] += xa[b] * cv[ul];
            }
            if (ch < 12) {          // W2 -> g[w], S_sy0
                const int ub = (ch - 8) * 8;
#pragma unroll
                for (int nn = 0; nn < 4; nn++) {
                    int n = gbase + nn; float acc = 0.0f;
#pragma unroll
                    for (int ul = 0; ul < 8; ul++)
                        acc += s_S[n * 192 + ub + ul] * ps[nn][ul];
                    s_out[n * 96 + 32 + w] += acc;
                }
            } else if (ch < 18) {   // W4 -> g[w], S_vd
                const int ub = (ch - 16) * 8;
#pragma unroll
                for (int nn = 0; nn < 4; nn++) {
                    int n = gbase + nn; float acc = 0.0f;
#pragma unroll
                    for (int ul = 0; ul < 8; ul++)
                        acc += s_S[n * 192 + 32 + ub + ul] * ps[nn][ul];
                    s_out[n * 96 + 32 + w] += acc;
                }
            } else if (ch < 22) {   // W5 -> v[w,k], S_w5 @48 + u*3+k
                const int ub = (ch - 18) * 8;
#pragma unroll
                for (int nn = 0; nn < 4; nn++) {
                    int n = gbase + nn; float a0 = 0, a1 = 0, a2 = 0;
#pragma unroll
                    for (int ul = 0; ul < 8; ul++) {
                        float p = ps[nn][ul];
                        const float* sp = s_S + n * 192 + 48 + (ub + ul) * 3;
                        a0 += sp[0] * p; a1 += sp[1] * p; a2 += sp[2] * p;
                    }
                    s_out[n * 96 + 48 + 3 * w + 0] += a0;
                    s_out[n * 96 + 48 + 3 * w + 1] += a1;
                    s_out[n * 96 + 48 + 3 * w + 2] += a2;
                }
            } else {                // W6 -> v[w,k], S_c6 @144 + k*16+u
                const int ub = (ch - 22) * 8;
#pragma unroll
                for (int nn = 0; nn < 4; nn++) {
                    int n = gbase + nn; float a0 = 0, a1 = 0, a2 = 0;
#pragma unroll
                    for (int ul = 0; ul < 8; ul++) {
                        float p = ps[nn][ul];
                        int u = ub + ul;
                        a0 += s_S[n * 192 + 144 + 0 * 16 + u] * p;
                        a1 += s_S[n * 192 + 144 + 1 * 16 + u] * p;
                        a2 += s_S[n * 192 + 144 + 2 * 16 + u] * p;
                    }
                    s_out[n * 96 + 48 + 3 * w + 0] += a0;
                    s_out[n * 96 + 48 + 3 * w + 1] += a1;
                    s_out[n * 96 + 48 + 3 * w + 2] += a2;
                }
            }
        }
        __syncthreads();
    }

    // ---- finalize ----
    if (tid < 64) {
        int n = n0 + tid;
        if (n < NN) {
            const float SQRT2 = 1.4142135623730951f;
            const float N0E = 0.14433756729740643f;
            float inv = 1.0f / fmaxf(g_cnt[n], 1.0f);
            const float* gs = g_sum + (size_t)n * 96;
            const float* so = s_out + tid * 96;
            const float* xr = x + (size_t)n * 80;
            float* o = out + (size_t)n * 80;
            float gg[16];
#pragma unroll
            for (int w = 0; w < 16; w++)
                gg[w] = SQRT2 * fmaxf((gs[32 + w] + N0E * so[32 + w]) * inv, 0.0f);
#pragma unroll
            for (int w = 0; w < 32; w++)
                o[w] = xr[w] + SQRT2 * fmaxf((gs[w] + N0E * so[w]) * inv, 0.0f);
#pragma unroll
            for (int w = 0; w < 16; w++)
#pragma unroll
                for (int k = 0; k < 3; k++)
                    o[32 + w * 3 + k] = xr[32 + w * 3 + k] +
                        (gs[48 + w * 3 + k] + N0E * so[48 + w * 3 + k]) * inv * gg[w];
        }
    }
}

// ---------------- launch ----------------
extern "C" void kernel_launch(void* const* d_in, const int* in_sizes, int n_in,
                              void* d_out, int out_size) {
    const float* x  = (const float*)d_in[0];
    const float* ea = (const float*)d_in[1];
    const float* Yj = (const float*)d_in[2];
    const int*   ei = (const int*)d_in[3];
    const float* wm = (const float*)d_in[4];
    float* out = (float*)d_out;

    cudaFuncSetAttribute(eq_prepM_kernel, cudaFuncAttributeMaxDynamicSharedMemorySize, 102912);
    cudaFuncSetAttribute(eq_edge_kernel,  cudaFuncAttributeMaxDynamicSharedMemorySize, 75520);
    cudaFuncSetAttribute(eq_node_kernel,  cudaFuncAttributeMaxDynamicSharedMemorySize, 98816);

    eq_zero_kernel<<<(NN * 192 + 255) / 256, 256>>>();
    eq_prepM_kernel<<<(NN + 63) / 64, 256, 102912>>>(x, wm);
    eq_edge_kernel<<<NE / 64, 256, 75520>>>(x, ea, Yj, ei, wm);
    eq_node_kernel<<<(NN + 63) / 64, 256, 98816>>>(x, wm, out);
}

// round 16
// speedup vs baseline: 1.4504x; 1.0245x over previous
#include <cuda_runtime.h>
#include <cstdint>

#define NN 12000
#define NE 120000

// ---------------- device scratch (allocation-free) ----------------
static __device__ float g_sum[NN * 96];
static __device__ float g_cnt[NN];
static __device__ float g_S[NN * 192];     // per-dst summed coefficients
static __device__ float g_M[NN * 256];     // per-src message matrix (vs Ye basis)

typedef unsigned long long ull;

// ---------------- f32x2 helpers ----------------
__device__ __forceinline__ ull packdup(float x) {
    ull r; asm("mov.b64 %0, {%1, %1};" : "=l"(r) : "f"(x)); return r;
}
__device__ __forceinline__ void fma2(ull& a, ull b, ull c) {
    asm("fma.rn.f32x2 %0, %1, %2, %0;" : "+l"(a) : "l"(b), "l"(c));
}
__device__ __forceinline__ ull mul2(ull a, ull b) {
    ull r; asm("mul.rn.f32x2 %0, %1, %2;" : "=l"(r) : "l"(a), "l"(b)); return r;
}
__device__ __forceinline__ ull add2(ull a, ull b) {
    ull r; asm("add.rn.f32x2 %0, %1, %2;" : "=l"(r) : "l"(a), "l"(b)); return r;
}
__device__ __forceinline__ float2 unpk(ull v) {
    float2 f; asm("mov.b64 {%0, %1}, %2;" : "=f"(f.x), "=f"(f.y) : "l"(v)); return f;
}

// ---------------- kernel 0: zero scratch ----------------
__global__ void eq_zero_kernel() {
    int i = blockIdx.x * 256 + threadIdx.x;
    if (i < NN * 96) g_sum[i] = 0.0f;
    if (i < NN * 192) g_S[i] = 0.0f;
    if (i < NN * 256) g_M[i] = 0.0f;
    if (i < NN) g_cnt[i] = 0.0f;
}

// ================= K1: build per-node M from src-rows of w_emb =================
// 64 nodes/block, 4 chunk-parts/node-group (grid 188*4), occupancy 2. smem floats:
//   s_xs[32][64]@0 (2048), s_xv[48][64]@2048 (3072), s_M[64][256]@5120 (16384),
//   s_ch[32][132]@21504 (4224). total 25728 f = 102912 B
__global__ __launch_bounds__(256, 2) void eq_prepM_kernel(
    const float* __restrict__ x, const float* __restrict__ wm)
{
    extern __shared__ float sm[];
    float* s_xs = sm;
    float* s_xv = sm + 2048;
    float* s_M  = sm + 5120;
    float* s_ch = sm + 21504;
    const int tid = threadIdx.x;
    const int n0 = (blockIdx.x >> 2) * 64;
    const int ch0 = (blockIdx.x & 3) * 6;

    for (int i = tid; i < 64 * 256; i += 256) s_M[i] = 0.0f;
    if (tid < 64) {
        int n = n0 + tid;
        bool v = n < NN;
        const float* xr = x + (size_t)n * 80;
#pragma unroll
        for (int k = 0; k < 32; k++) s_xs[k * 64 + tid] = v ? xr[k] : 0.0f;
#pragma unroll
        for (int u = 0; u < 16; u++)
#pragma unroll
            for (int k = 0; k < 3; k++)
                s_xv[(k * 16 + u) * 64 + tid] = v ? xr[32 + u * 3 + k] : 0.0f;
    }
    __syncthreads();

    const float RS = 0.08838834764831845f;       // 1/sqrt(128)
    const float INV3 = 0.57735026918962576f;     // 1/sqrt(3)

    for (int ch = ch0; ch < ch0 + 6; ch++) {
        {   // load chunk: wm rows 32..63 (src rows), cols ch*128.., scaled by RS
            int r = tid >> 3, cc = (tid & 7) * 16;
            const float* src = wm + (size_t)(32 + r) * 3072 + ch * 128 + cc;
            float* dstp = s_ch + r * 132 + cc;
#pragma unroll
            for (int i = 0; i < 4; i++) {
                float4 v = *(const float4*)(src + i * 4);
                dstp[i * 4 + 0] = v.x * RS; dstp[i * 4 + 1] = v.y * RS;
                dstp[i * 4 + 2] = v.z * RS; dstp[i * 4 + 3] = v.w * RS;
            }
        }
        __syncthreads();

        if (ch < 8 || (ch >= 12 && ch < 16)) {
            // W=32 blocks (W1, W3): 8 groups x 8 nodes, ps[8][4]
            const int w = tid & 31, gbase = (tid >> 5) * 8;
            float ps[8][4];
#pragma unroll
            for (int nn = 0; nn < 8; nn++)
#pragma unroll
                for (int ul = 0; ul < 4; ul++) ps[nn][ul] = 0.0f;
            for (int k = 0; k < 32; k++) {
                float cv0 = s_ch[k * 132 + w], cv1 = s_ch[k * 132 + 32 + w];
                float cv2 = s_ch[k * 132 + 64 + w], cv3 = s_ch[k * 132 + 96 + w];
                const float4* xp = (const float4*)(s_xs + k * 64 + gbase);
#pragma unroll
                for (int q = 0; q < 2; q++) {
                    float4 xv4 = xp[q];
                    float xa[4] = {xv4.x, xv4.y, xv4.z, xv4.w};
#pragma unroll
                    for (int b = 0; b < 4; b++) {
                        int nn = q * 4 + b;
                        ps[nn][0] += xa[b] * cv0; ps[nn][1] += xa[b] * cv1;
                        ps[nn][2] += xa[b] * cv2; ps[nn][3] += xa[b] * cv3;
                    }
                }
            }
            if (ch < 8) {       // W1 -> s0[w]
#pragma unroll
                for (int nn = 0; nn < 8; nn++) {
                    int n = gbase + nn; float acc = 0.0f;
#pragma unroll
                    for (int ul = 0; ul < 4; ul++)
                        acc += s_xs[(ch * 4 + ul) * 64 + n] * ps[nn][ul];
                    s_M[n * 256 + w] += acc;
                }
            } else {            // W3 -> s_j[w]
#pragma unroll
                for (int nn = 0; nn < 8; nn++) {
                    int n = gbase + nn; float a0 = 0, a1 = 0, a2 = 0;
#pragma unroll
                    for (int ul = 0; ul < 4; ul++) {
                        int u = (ch - 12) * 4 + ul; float p = ps[nn][ul];
                        a0 += s_xv[(0 * 16 + u) * 64 + n] * p;
                        a1 += s_xv[(1 * 16 + u) * 64 + n] * p;
                        a2 += s_xv[(2 * 16 + u) * 64 + n] * p;
                    }
                    s_M[n * 256 + 96 + w]  += a0 * INV3;
                    s_M[n * 256 + 128 + w] += a1 * INV3;
                    s_M[n * 256 + 160 + w] += a2 * INV3;
                }
            }
        } else {
            // W=16 blocks: 16 groups x 4 nodes, ps[4][8]
            const int w = tid & 15, gbase = (tid >> 4) * 4;
            float ps[4][8];
#pragma unroll
            for (int nn = 0; nn < 4; nn++)
#pragma unroll
                for (int ul = 0; ul < 8; ul++) ps[nn][ul] = 0.0f;
            for (int k = 0; k < 32; k++) {
                float cv[8];
#pragma unroll
                for (int ul = 0; ul < 8; ul++) cv[ul] = s_ch[k * 132 + ul * 16 + w];
                float4 xv4 = *(const float4*)(s_xs + k * 64 + gbase);
                float xa[4] = {xv4.x, xv4.y, xv4.z, xv4.w};
#pragma unroll
                for (int b = 0; b < 4; b++)
#pragma unroll
                    for (int ul = 0; ul < 8; ul++) ps[b][ul] += xa[b] * cv[ul];
            }
            if (ch < 12) {          // W2 -> g0[w]
#pragma unroll
                for (int nn = 0; nn < 4; nn++) {
                    int n = gbase + nn; float acc = 0.0f;
#pragma unroll
                    for (int ul = 0; ul < 8; ul++)
                        acc += s_xs[((ch - 8) * 8 + ul) * 64 + n] * ps[nn][ul];
                    s_M[n * 256 + 32 + w] += acc;
                }
            } else if (ch < 18) {   // W4 -> g_j[w]
#pragma unroll
                for (int nn = 0; nn < 4; nn++) {
                    int n = gbase + nn; float a0 = 0, a1 = 0, a2 = 0;
#pragma unroll
                    for (int ul = 0; ul < 8; ul++) {
                        int u = (ch - 16) * 8 + ul; float p = ps[nn][ul];
                        a0 += s_xv[(0 * 16 + u) * 64 + n] * p;
                        a1 += s_xv[(1 * 16 + u) * 64 + n] * p;
                        a2 += s_xv[(2 * 16 + u) * 64 + n] * p;
                    }
                    s_M[n * 256 + 192 + w] += a0 * INV3;
                    s_M[n * 256 + 208 + w] += a1 * INV3;
                    s_M[n * 256 + 224 + w] += a2 * INV3;
                }
            } else if (ch < 22) {   // W5 -> t5[w]
#pragma unroll
                for (int nn = 0; nn < 4; nn++) {
                    int n = gbase + nn; float acc = 0.0f;
#pragma unroll
                    for (int ul = 0; ul < 8; ul++)
                        acc += s_xs[((ch - 18) * 8 + ul) * 64 + n] * ps[nn][ul];
                    s_M[n * 256 + 240 + w] += acc;
                }
            } else {                // W6 -> v0[w,k]
#pragma unroll
                for (int nn = 0; nn < 4; nn++) {
                    int n = gbase + nn; float a0 = 0, a1 = 0, a2 = 0;
#pragma unroll
                    for (int ul = 0; ul < 8; ul++) {
                        int u = (ch - 22) * 8 + ul; float p = ps[nn][ul];
                        a0 += s_xv[(0 * 16 + u) * 64 + n] * p;
                        a1 += s_xv[(1 * 16 + u) * 64 + n] * p;
                        a2 += s_xv[(2 * 16 + u) * 64 + n] * p;
                    }
                    s_M[n * 256 + 48 + 3 * w + 0] += a0;
                    s_M[n * 256 + 48 + 3 * w + 1] += a1;
                    s_M[n * 256 + 48 + 3 * w + 2] += a2;
                }
            }
        }
        __syncthreads();
    }

    for (int i = tid; i < 64 * 256; i += 256) {
        int n = n0 + (i >> 8);
        float v = s_M[i];
        if (n < NN && v != 0.0f) atomicAdd(&g_M[(size_t)n * 256 + (i & 255)], v);
    }
}

// ================= K2: edge kernel (ea-GEMM K=64 + termB + S atomics) =================
// 64 edges / block, 256 threads, 24 passes of 128 cols, lane owns 4 consecutive cols.
__global__ __launch_bounds__(256, 2) void eq_edge_kernel(
    const float* __restrict__ x, const float* __restrict__ ea,
    const float* __restrict__ Yij, const int* __restrict__ eidx,
    const float* __restrict__ wm)
{
    extern __shared__ float sm[];
    float* s_emb = sm;
    float* s_msg = sm + 4096;
    float* s_sy0 = sm + 10240;
    float* s_vd  = sm + 12288;
    float* s_x1s = sm + 13312;
    float* s_c6  = sm + 15360;
    float* s_y1  = sm + 18432;
    float* s_y0  = sm + 18688;
    int* s_dst = (int*)(sm + 18752);
    int* s_src = (int*)(sm + 18816);

    const int tid = threadIdx.x;
    const int eb0 = blockIdx.x << 6;

    if (tid < 64) {
        s_dst[tid] = eidx[eb0 + tid];
        s_src[tid] = eidx[NE + eb0 + tid];
    }
    __syncthreads();

    // ---- emb staging: edge_attr only (k=0..63), scaled by 1/sqrt(128) ----
    {
        const int el = tid & 63, part = tid >> 6;   // 4 parts x 16 k
        const float RS = 0.08838834764831845f;
        const float* src = ea + (size_t)(eb0 + el) * 64 + part * 16;
        const int kb = part * 16;
#pragma unroll
        for (int i = 0; i < 4; i++) {
            float4 v = *(const float4*)(src + i * 4);
            s_emb[(kb + i * 4 + 0) * 64 + el] = v.x * RS;
            s_emb[(kb + i * 4 + 1) * 64 + el] = v.y * RS;
            s_emb[(kb + i * 4 + 2) * 64 + el] = v.z * RS;
            s_emb[(kb + i * 4 + 3) * 64 + el] = v.w * RS;
        }
    }
    // ---- per-edge coefficients ----
    if (tid < 64) {
        const int e = tid;
        float4 Y = *(const float4*)(Yij + (size_t)(eb0 + e) * 4);
        s_y0[e] = Y.x;
        s_y1[e * 4 + 0] = Y.y; s_y1[e * 4 + 1] = Y.z; s_y1[e * 4 + 2] = Y.w;
        const float* xr = x + (size_t)s_src[e] * 80;
        const float INV3 = 0.57735026918962576f;
#pragma unroll
        for (int u = 0; u < 32; u++) {
            float xs = xr[u];
            s_x1s[u * 64 + e] = xs;
            s_sy0[u * 64 + e] = xs * Y.x;
        }
#pragma unroll
        for (int u = 0; u < 16; u++) {
            float v0 = xr[32 + u * 3], v1 = xr[33 + u * 3], v2 = xr[34 + u * 3];
            s_vd[u * 64 + e] = (v0 * Y.y + v1 * Y.z + v2 * Y.w) * INV3;
            s_c6[(u)      * 64 + e] = v0 * Y.x;
            s_c6[(16 + u) * 64 + e] = v1 * Y.x;
            s_c6[(32 + u) * 64 + e] = v2 * Y.x;
        }
    }
    __syncthreads();

    // ---- term B: s_msg = M[src] applied to Ye ----
    for (int i = tid; i < 64 * 96; i += 256) {
        int e = i / 96, w = i - e * 96;
        const float* Mr = g_M + (size_t)s_src[e] * 256;
        float y0 = s_y0[e];
        float ya = s_y1[e * 4 + 0], yb = s_y1[e * 4 + 1], yc = s_y1[e * 4 + 2];
        float val;
        if (w < 32) {
            val = y0 * Mr[w] + ya * Mr[96 + w] + yb * Mr[128 + w] + yc * Mr[160 + w];
        } else if (w < 48) {
            int wg = w - 32;
            val = y0 * Mr[32 + wg] + ya * Mr[192 + wg] + yb * Mr[208 + wg] + yc * Mr[224 + wg];
        } else {
            int m = w - 48, wv = m / 3, k = m - wv * 3;
            val = y0 * Mr[48 + m] + s_y1[e * 4 + k] * Mr[240 + wv];
        }
        s_msg[e * 96 + w] = val;
    }
    __syncthreads();

    const int ct = tid & 31;
    const int e0 = (tid >> 5) << 3;

    ull acc[4][4], macc[4][4];
#pragma unroll
    for (int p = 0; p < 4; p++)
#pragma unroll
        for (int j = 0; j < 4; j++) macc[p][j] = 0ull;

    const float* wbase = wm + (size_t)64 * 3072 + ct * 4;

    for (int pass = 0; pass < 24; ++pass) {
#pragma unroll
        for (int p = 0; p < 4; p++)
#pragma unroll
            for (int j = 0; j < 4; j++) acc[p][j] = 0ull;

        const float* wp = wbase + pass * 128;
#pragma unroll 4
        for (int c = 0; c < 64; ++c) {
            float4 wv = *(const float4*)(wp + (size_t)c * 3072);
            ull w0 = packdup(wv.x), w1 = packdup(wv.y), w2 = packdup(wv.z), w3 = packdup(wv.w);
            const ull* ep = (const ull*)(s_emb + (c << 6) + e0);
            ull q0 = ep[0], q1 = ep[1], q2 = ep[2], q3 = ep[3];
            fma2(acc[0][0], q0, w0); fma2(acc[0][1], q0, w1); fma2(acc[0][2], q0, w2); fma2(acc[0][3], q0, w3);
            fma2(acc[1][0], q1, w0); fma2(acc[1][1], q1, w1); fma2(acc[1][2], q1, w2); fma2(acc[1][3], q1, w3);
            fma2(acc[2][0], q2, w0); fma2(acc[2][1], q2, w1); fma2(acc[2][2], q2, w2); fma2(acc[2][3], q2, w3);
            fma2(acc[3][0], q3, w0); fma2(acc[3][1], q3, w1); fma2(acc[3][2], q3, w2); fma2(acc[3][3], q3, w3);
        }

        if (pass < 8) {               // W1
            int u = pass * 4 + (ct >> 3);
            const ull* cp = (const ull*)(s_sy0 + (u << 6) + e0);
#pragma unroll
            for (int p = 0; p < 4; p++) { ull c2 = cp[p];
#pragma unroll
                for (int j = 0; j < 4; j++) fma2(macc[p][j], c2, acc[p][j]); }
            if (pass == 7) {
#pragma unroll
                for (int p = 0; p < 4; p++)
#pragma unroll
                    for (int j = 0; j < 4; j++) {
                        ull v = macc[p][j];
                        v = add2(v, __shfl_xor_sync(0xffffffffu, v, 8));
                        v = add2(v, __shfl_xor_sync(0xffffffffu, v, 16));
                        if (ct < 8) {
                            float2 f = unpk(v);
                            int w = ct * 4 + j;
                            s_msg[(e0 + 2 * p) * 96 + w] += f.x;
                            s_msg[(e0 + 2 * p + 1) * 96 + w] += f.y;
                        }
                        macc[p][j] = 0ull;
                    }
            }
        } else if (pass < 12) {       // W2
            int u = (pass - 8) * 8 + (ct >> 2);
            const ull* cp = (const ull*)(s_sy0 + (u << 6) + e0);
#pragma unroll
            for (int p = 0; p < 4; p++) { ull c2 = cp[p];
#pragma unroll
                for (int j = 0; j < 4; j++) fma2(macc[p][j], c2, acc[p][j]); }
            if (pass == 11) {
#pragma unroll
                for (int p = 0; p < 4; p++)
#pragma unroll
                    for (int j = 0; j < 4; j++) {
                        ull v = macc[p][j];
                        v = add2(v, __shfl_xor_sync(0xffffffffu, v, 4));
                        v = add2(v, __shfl_xor_sync(0xffffffffu, v, 8));
                        v = add2(v, __shfl_xor_sync(0xffffffffu, v, 16));
                        if (ct < 4) {
                            float2 f = unpk(v);
                            int w = 32 + ct * 4 + j;
                            s_msg[(e0 + 2 * p) * 96 + w] += f.x;
                            s_msg[(e0 + 2 * p + 1) * 96 + w] += f.y;
                        }
                        macc[p][j] = 0ull;
                    }
            }
        } else if (pass < 16) {       // W3
            int u = (pass - 12) * 4 + (ct >> 3);
            const ull* cp = (const ull*)(s_vd + (u << 6) + e0);
#pragma unroll
            for (int p = 0; p < 4; p++) { ull c2 = cp[p];
#pragma unroll
                for (int j = 0; j < 4; j++) fma2(macc[p][j], c2, acc[p][j]); }
            if (pass == 15) {
#pragma unroll
                for (int p = 0; p < 4; p++)
#pragma unroll
                    for (int j = 0; j < 4; j++) {
                        ull v = macc[p][j];
                        v = add2(v, __shfl_xor_sync(0xffffffffu, v, 8));
                        v = add2(v, __shfl_xor_sync(0xffffffffu, v, 16));
                        if (ct < 8) {
                            float2 f = unpk(v);
                            int w = ct * 4 + j;
                            s_msg[(e0 + 2 * p) * 96 + w] += f.x;
                            s_msg[(e0 + 2 * p + 1) * 96 + w] += f.y;
                        }
                        macc[p][j] = 0ull;
                    }
            }
        } else if (pass < 18) {       // W4
            int u = (pass - 16) * 8 + (ct >> 2);
            const ull* cp = (const ull*)(s_vd + (u << 6) + e0);
#pragma unroll
            for (int p = 0; p < 4; p++) { ull c2 = cp[p];
#pragma unroll
                for (int j = 0; j < 4; j++) fma2(macc[p][j], c2, acc[p][j]); }
            if (pass == 17) {
#pragma unroll
                for (int p = 0; p < 4; p++)
#pragma unroll
                    for (int j = 0; j < 4; j++) {
                        ull v = macc[p][j];
                        v = add2(v, __shfl_xor_sync(0xffffffffu, v, 4));
                        v = add2(v, __shfl_xor_sync(0xffffffffu, v, 8));
                        v = add2(v, __shfl_xor_sync(0xffffffffu, v, 16));
                        if (ct < 4) {
                            float2 f = unpk(v);
                            int w = 32 + ct * 4 + j;
                            s_msg[(e0 + 2 * p) * 96 + w] += f.x;
                            s_msg[(e0 + 2 * p + 1) * 96 + w] += f.y;
                        }
                        macc[p][j] = 0ull;
                    }
            }
        } else if (pass < 22) {       // W5 (x y1[k])
            int u = (pass - 18) * 8 + (ct >> 2);
            const ull* cp = (const ull*)(s_x1s + (u << 6) + e0);
#pragma unroll
            for (int p = 0; p < 4; p++) { ull c2 = cp[p];
#pragma unroll
                for (int j = 0; j < 4; j++) fma2(macc[p][j], c2, acc[p][j]); }
            if (pass == 21) {
#pragma unroll
                for (int p = 0; p < 4; p++)
#pragma unroll
                    for (int j = 0; j < 4; j++) {
                        ull v = macc[p][j];
                        v = add2(v, __shfl_xor_sync(0xffffffffu, v, 4));
                        v = add2(v, __shfl_xor_sync(0xffffffffu, v, 8));
                        v = add2(v, __shfl_xor_sync(0xffffffffu, v, 16));
                        if (ct < 4) {
                            float2 f = unpk(v);
                            int w = ct * 4 + j;
                            int ex = e0 + 2 * p;
#pragma unroll
                            for (int k = 0; k < 3; k++) {
                                s_msg[ex * 96 + 48 + w * 3 + k] += f.x * s_y1[ex * 4 + k];
                                s_msg[(ex + 1) * 96 + 48 + w * 3 + k] += f.y * s_y1[(ex + 1) * 4 + k];
                            }
                        }
                        macc[p][j] = 0ull;
                    }
            }
        } else {                      // W6
            int u = (pass - 22) * 8 + (ct >> 2);
#pragma unroll
            for (int k = 0; k < 3; k++) {
                const ull* cp = (const ull*)(s_c6 + ((k * 16 + u) << 6) + e0);
#pragma unroll
                for (int p = 0; p < 4; p++) {
                    ull c2 = cp[p];
#pragma unroll
                    for (int j = 0; j < 4; j++) {
                        ull v = mul2(acc[p][j], c2);
                        v = add2(v, __shfl_xor_sync(0xffffffffu, v, 4));
                        v = add2(v, __shfl_xor_sync(0xffffffffu, v, 8));
                        v = add2(v, __shfl_xor_sync(0xffffffffu, v, 16));
                        if (ct < 4) {
                            float2 f = unpk(v);
                            int w = ct * 4 + j;
                            s_msg[(e0 + 2 * p) * 96 + 48 + w * 3 + k] += f.x;
                            s_msg[(e0 + 2 * p + 1) * 96 + 48 + w * 3 + k] += f.y;
                        }
                    }
                }
            }
        }
    }

    // ---- scatter: messages (terms B+C), coef sums S, counts ----
    __syncthreads();
    const float N0E = 0.14433756729740643f;   // 1/sqrt(48)
    for (int i = tid; i < 64 * 96; i += 256) {
        int e = i / 96, w = i - e * 96;
        atomicAdd(&g_sum[(size_t)s_dst[e] * 96 + w], s_msg[i] * N0E);
    }
    for (int i = tid; i < 64 * 192; i += 256) {
        int e = i / 192, q = i - e * 192;
        float val;
        if (q < 32) val = s_sy0[q * 64 + e];
        else if (q < 48) val = s_vd[(q - 32) * 64 + e];
        else if (q < 144) {
            int m = q - 48, u = m / 3, k = m - u * 3;
            val = s_x1s[u * 64 + e] * s_y1[e * 4 + k];
        } else val = s_c6[(q - 144) * 64 + e];
        atomicAdd(&g_S[(size_t)s_dst[e] * 192 + q], val);
    }
    if (tid < 64) atomicAdd(&g_cnt[s_dst[tid]], 1.0f);
}

// ================= K3: dst-term contraction (chunk-split, atomics into g_sum) =================
// 64 nodes/block, 4 chunk-parts (grid 188*4), occupancy 2. smem floats:
//   s_xs[32][64]@0 (2048), s_S[64][192]@2048 (12288), s_out[64][96]@14336 (6144),
//   s_ch[32][132]@20480 (4224). total 24704 f = 98816 B
__global__ __launch_bounds__(256, 2) void eq_nodeA_kernel(
    const float* __restrict__ x, const float* __restrict__ wm)
{
    extern __shared__ float sm[];
    float* s_xs  = sm;
    float* s_S   = sm + 2048;
    float* s_out = sm + 14336;
    float* s_ch  = sm + 20480;
    const int tid = threadIdx.x;
    const int n0 = (blockIdx.x >> 2) * 64;
    const int ch0 = (blockIdx.x & 3) * 6;

    for (int i = tid; i < 64 * 96; i += 256) s_out[i] = 0.0f;
    for (int i = tid; i < 64 * 192; i += 256) {
        int n = n0 + (i / 192);
        s_S[i] = (n < NN) ? g_S[(size_t)n * 192 + (i % 192)] : 0.0f;
    }
    if (tid < 64) {
        int n = n0 + tid;
        bool v = n < NN;
        const float* xr = x + (size_t)n * 80;
#pragma unroll
        for (int k = 0; k < 32; k++) s_xs[k * 64 + tid] = v ? xr[k] : 0.0f;
    }
    __syncthreads();

    const float RS = 0.08838834764831845f;

    for (int ch = ch0; ch < ch0 + 6; ch++) {
        {   // load chunk: wm rows 0..31 (dst rows)
            int r = tid >> 3, cc = (tid & 7) * 16;
            const float* src = wm + (size_t)r * 3072 + ch * 128 + cc;
            float* dstp = s_ch + r * 132 + cc;
#pragma unroll
            for (int i = 0; i < 4; i++) {
                float4 v = *(const float4*)(src + i * 4);
                dstp[i * 4 + 0] = v.x * RS; dstp[i * 4 + 1] = v.y * RS;
                dstp[i * 4 + 2] = v.z * RS; dstp[i * 4 + 3] = v.w * RS;
            }
        }
        __syncthreads();

        if (ch < 8 || (ch >= 12 && ch < 16)) {
            const int w = tid & 31, gbase = (tid >> 5) * 8;
            float ps[8][4];
#pragma unroll
            for (int nn = 0; nn < 8; nn++)
#pragma unroll
                for (int ul = 0; ul < 4; ul++) ps[nn][ul] = 0.0f;
            for (int k = 0; k < 32; k++) {
                float cv0 = s_ch[k * 132 + w], cv1 = s_ch[k * 132 + 32 + w];
                float cv2 = s_ch[k * 132 + 64 + w], cv3 = s_ch[k * 132 + 96 + w];
                const float4* xp = (const float4*)(s_xs + k * 64 + gbase);
#pragma unroll
                for (int q = 0; q < 2; q++) {
                    float4 xv4 = xp[q];
                    float xa[4] = {xv4.x, xv4.y, xv4.z, xv4.w};
#pragma unroll
                    for (int b = 0; b < 4; b++) {
                        int nn = q * 4 + b;
                        ps[nn][0] += xa[b] * cv0; ps[nn][1] += xa[b] * cv1;
                        ps[nn][2] += xa[b] * cv2; ps[nn][3] += xa[b] * cv3;
                    }
                }
            }
            const int ub = (ch < 8) ? ch * 4 : (ch - 12) * 4;
            const int soff = (ch < 8) ? 0 : 32;
#pragma unroll
            for (int nn = 0; nn < 8; nn++) {
                int n = gbase + nn; float acc = 0.0f;
#pragma unroll
                for (int ul = 0; ul < 4; ul++)
                    acc += s_S[n * 192 + soff + ub + ul] * ps[nn][ul];
                s_out[n * 96 + w] += acc;
            }
        } else {
            const int w = tid & 15, gbase = (tid >> 4) * 4;
            float ps[4][8];
#pragma unroll
            for (int nn = 0; nn < 4; nn++)
#pragma unroll
                for (int ul = 0; ul < 8; ul++) ps[nn][ul] = 0.0f;
            for (int k = 0; k < 32; k++) {
                float cv[8];
#pragma unroll
                for (int ul = 0; ul < 8; ul++) cv[ul] = s_ch[k * 132 + ul * 16 + w];
                float4 xv4 = *(const float4*)(s_xs + k * 64 + gbase);
                float xa[4] = {xv4.x, xv4.y, xv4.z, xv4.w};
#pragma unroll
                for (int b = 0; b < 4; b++)
#pragma unroll
                    for (int ul = 0; ul < 8; ul++) ps[b][ul] += xa[b] * cv[ul];
            }
            if (ch < 12) {          // W2
                const int ub = (ch - 8) * 8;
#pragma unroll
                for (int nn = 0; nn < 4; nn++) {
                    int n = gbase + nn; float acc = 0.0f;
#pragma unroll
                    for (int ul = 0; ul < 8; ul++)
                        acc += s_S[n * 192 + ub + ul] * ps[nn][ul];
                    s_out[n * 96 + 32 + w] += acc;
                }
            } else if (ch < 18) {   // W4
                const int ub = (ch - 16) * 8;
#pragma unroll
                for (int nn = 0; nn < 4; nn++) {
                    int n = gbase + nn; float acc = 0.0f;
#pragma unroll
                    for (int ul = 0; ul < 8; ul++)
                        acc += s_S[n * 192 + 32 + ub + ul] * ps[nn][ul];
                    s_out[n * 96 + 32 + w] += acc;
                }
            } else if (ch < 22) {   // W5
                const int ub = (ch - 18) * 8;
#pragma unroll
                for (int nn = 0; nn < 4; nn++) {
                    int n = gbase + nn; float a0 = 0, a1 = 0, a2 = 0;
#pragma unroll
                    for (int ul = 0; ul < 8; ul++) {
                        float p = ps[nn][ul];
                        const float* sp = s_S + n * 192 + 48 + (ub + ul) * 3;
                        a0 += sp[0] * p; a1 += sp[1] * p; a2 += sp[2] * p;
                    }
                    s_out[n * 96 + 48 + 3 * w + 0] += a0;
                    s_out[n * 96 + 48 + 3 * w + 1] += a1;
                    s_out[n * 96 + 48 + 3 * w + 2] += a2;
                }
            } else {                // W6
                const int ub = (ch - 22) * 8;
#pragma unroll
                for (int nn = 0; nn < 4; nn++) {
                    int n = gbase + nn; float a0 = 0, a1 = 0, a2 = 0;
#pragma unroll
                    for (int ul = 0; ul < 8; ul++) {
                        float p = ps[nn][ul];
                        int u = ub + ul;
                        a0 += s_S[n * 192 + 144 + 0 * 16 + u] * p;
                        a1 += s_S[n * 192 + 144 + 1 * 16 + u] * p;
                        a2 += s_S[n * 192 + 144 + 2 * 16 + u] * p;
                    }
                    s_out[n * 96 + 48 + 3 * w + 0] += a0;
                    s_out[n * 96 + 48 + 3 * w + 1] += a1;
                    s_out[n * 96 + 48 + 3 * w + 2] += a2;
                }
            }
        }
        __syncthreads();
    }

    const float N0E = 0.14433756729740643f;
    for (int i = tid; i < 64 * 96; i += 256) {
        int n = n0 + (i / 96);
        float v = s_out[i];
        if (n < NN && v != 0.0f) atomicAdd(&g_sum[(size_t)n * 96 + (i % 96)], v * N0E);
    }
}

// ================= K4: finalize =================
// 128 nodes/block (94 blocks). smem: s_gs[128][96] (12288), s_o[128][80] (10240) = 90112 B
__global__ __launch_bounds__(256, 2) void eq_fin_kernel(
    const float* __restrict__ x, float* __restrict__ out)
{
    extern __shared__ float sm[];
    float* s_gs = sm;
    float* s_o  = sm + 12288;
    const int tid = threadIdx.x;
    const int n0 = blockIdx.x * 128;

    for (int i = tid; i < 128 * 96; i += 256) {
        int n = n0 + (i / 96);
        s_gs[i] = (n < NN) ? g_sum[(size_t)n * 96 + (i % 96)] : 0.0f;
    }
    __syncthreads();

    if (tid < 128) {
        int n = n0 + tid;
        if (n < NN) {
            const float SQRT2 = 1.4142135623730951f;
            float inv = 1.0f / fmaxf(g_cnt[n], 1.0f);
            const float* gs = s_gs + tid * 96;
            const float* xr = x + (size_t)n * 80;
            float* o = s_o + tid * 80;
            float gg[16];
#pragma unroll
            for (int w = 0; w < 16; w++) gg[w] = SQRT2 * fmaxf(gs[32 + w] * inv, 0.0f);
#pragma unroll
            for (int w = 0; w < 32; w++) o[w] = xr[w] + SQRT2 * fmaxf(gs[w] * inv, 0.0f);
#pragma unroll
            for (int w = 0; w < 16; w++)
#pragma unroll
                for (int k = 0; k < 3; k++)
                    o[32 + w * 3 + k] = xr[32 + w * 3 + k] + gs[48 + w * 3 + k] * inv * gg[w];
        }
    }
    __syncthreads();

    const int lim = min(128, NN - n0) * 80;
    for (int i = tid; i < lim; i += 256)
        out[(size_t)n0 * 80 + i] = s_o[i];
}

// ---------------- launch ----------------
extern "C" void kernel_launch(void* const* d_in, const int* in_sizes, int n_in,
                              void* d_out, int out_size) {
    const float* x  = (const float*)d_in[0];
    const float* ea = (const float*)d_in[1];
    const float* Yj = (const float*)d_in[2];
    const int*   ei = (const int*)d_in[3];
    const float* wm = (const float*)d_in[4];
    float* out = (float*)d_out;

    cudaFuncSetAttribute(eq_prepM_kernel, cudaFuncAttributeMaxDynamicSharedMemorySize, 102912);
    cudaFuncSetAttribute(eq_edge_kernel,  cudaFuncAttributeMaxDynamicSharedMemorySize, 75520);
    cudaFuncSetAttribute(eq_nodeA_kernel, cudaFuncAttributeMaxDynamicSharedMemorySize, 98816);
    cudaFuncSetAttribute(eq_fin_kernel,   cudaFuncAttributeMaxDynamicSharedMemorySize, 90112);

    eq_zero_kernel<<<(NN * 256 + 255) / 256, 256>>>();
    eq_prepM_kernel<<<((NN + 63) / 64) * 4, 256, 102912>>>(x, wm);
    eq_edge_kernel<<<NE / 64, 256, 75520>>>(x, ea, Yj, ei, wm);
    eq_nodeA_kernel<<<((NN + 63) / 64) * 4, 256, 98816>>>(x, wm);
    eq_fin_kernel<<<(NN + 127) / 128, 256, 90112>>>(x, out);
}